// round 1
// baseline (speedup 1.0000x reference)
#include <cuda_runtime.h>

#define B_   16
#define C_   4
#define HH   256
#define WW   256
#define HID  64
#define PCH  116          // C_*(3*10-1)
#define HW   (HH*WW)      // 65536

// ---------------- device scratch (no allocations allowed) ----------------
__device__ float g_hid[B_ * HID * HW];        // 268 MB
__device__ float g_p  [B_ * PCH * HW];        // 486 MB
__device__ float g_partial[B_ * C_ * HH];     // 16384 partial lad sums

// =========================================================================
// conv1: clean[16,4,256,256] -> relu(conv3x3) -> g_hid[16,64,256,256]
// block = one row (256 x) for fixed (b, oc-group-of-4). 4 accumulators/thread.
// =========================================================================
__global__ void __launch_bounds__(256) conv1_kernel(
    const float* __restrict__ clean,
    const float* __restrict__ W1,
    const float* __restrict__ b1)
{
    __shared__ float2 s_wp[36 * 2];   // [k][half] : (oc0,oc1) / (oc2,oc3)
    __shared__ float  s_b[4];

    const int y = blockIdx.x;
    const int g = blockIdx.y;         // oc group: ocs 4g..4g+3
    const int b = blockIdx.z;
    const int tid = threadIdx.x;

    if (tid < 72) {
        int k = tid >> 1, half = tid & 1;
        int oc0 = g * 4 + 2 * half;
        s_wp[2 * k + half] = make_float2(W1[oc0 * 36 + k], W1[(oc0 + 1) * 36 + k]);
    }
    if (tid < 4) s_b[tid] = b1[g * 4 + tid];
    __syncthreads();

    float2 aA = make_float2(s_b[0], s_b[1]);
    float2 aB = make_float2(s_b[2], s_b[3]);

    #pragma unroll
    for (int ic = 0; ic < 4; ic++) {
        #pragma unroll
        for (int ky = 0; ky < 3; ky++) {
            const int yy = y + ky - 1;
            const bool yok = ((unsigned)yy < 256u);
            #pragma unroll
            for (int kx = 0; kx < 3; kx++) {
                const int xx = tid + kx - 1;
                float v = 0.f;
                if (yok && (unsigned)xx < 256u)
                    v = clean[((b * 4 + ic) * HW) + yy * WW + xx];
                const int k = ic * 9 + ky * 3 + kx;
                float2 wA = s_wp[2 * k], wB = s_wp[2 * k + 1];
                aA.x = fmaf(v, wA.x, aA.x); aA.y = fmaf(v, wA.y, aA.y);
                aB.x = fmaf(v, wB.x, aB.x); aB.y = fmaf(v, wB.y, aB.y);
            }
        }
    }
    const int o = ((b * HID + g * 4) * HW) + y * WW + tid;
    g_hid[o         ] = fmaxf(aA.x, 0.f);
    g_hid[o +     HW] = fmaxf(aA.y, 0.f);
    g_hid[o + 2 * HW] = fmaxf(aB.x, 0.f);
    g_hid[o + 3 * HW] = fmaxf(aB.y, 0.f);
}

// =========================================================================
// conv2: g_hid -> g_p[16,116,256,256].
// Tile: 16(x) x 32(y), 256 threads; each thread owns 2 y-pixels.
// oc handled in groups of 4 (29 groups); weights as float2 broadcast pairs.
// Dynamic smem: s_in[64][34][18] fp32 (156.7KB) + 1152 float2 + 4 bias.
// =========================================================================
#define S2_IN   (64 * 34 * 18)                  // 39168 floats
#define SMEM2   (S2_IN * 4 + 1152 * 8 + 16)     // 165,904 bytes

__global__ void __launch_bounds__(256) conv2_kernel(
    const float* __restrict__ W2,
    const float* __restrict__ b2)
{
    extern __shared__ float smem[];
    float*  s_in = smem;                         // [ic][row 0..33][col 0..17]
    float2* s_wp = (float2*)(smem + S2_IN);      // [k*2 + half]
    float*  s_b  = (float*)(s_wp + 1152);

    const int x0 = blockIdx.x * 16;
    const int y0 = blockIdx.y * 32;
    const int b  = blockIdx.z;
    const int tid = threadIdx.x;

    // load input tile (zero-padded halo)
    for (int i = tid; i < S2_IN; i += 256) {
        const int ic = i / 612;
        const int r  = (i - ic * 612) / 18;
        const int cc = i % 18;
        const int yy = y0 + r - 1, xx = x0 + cc - 1;
        float v = 0.f;
        if ((unsigned)yy < 256u && (unsigned)xx < 256u)
            v = g_hid[((b * HID + ic) * HW) + yy * WW + xx];
        s_in[i] = v;
    }

    const int tx = tid & 15;
    const int ty = tid >> 4;    // 0..15 ; pixels (y0+ty) and (y0+ty+16)

    for (int g29 = 0; g29 < 29; g29++) {
        // load 4 oc's weights, interleaved float2 pairs
        for (int e = tid; e < 1152; e += 256) {
            const int k = e >> 1, half = e & 1;
            const int oc0 = (g29 * 4 + 2 * half);
            s_wp[e] = make_float2(W2[oc0 * 576 + k], W2[(oc0 + 1) * 576 + k]);
        }
        if (tid < 4) s_b[tid] = b2[g29 * 4 + tid];
        __syncthreads();

        float2 p0A = make_float2(s_b[0], s_b[1]);
        float2 p0B = make_float2(s_b[2], s_b[3]);
        float2 p1A = p0A, p1B = p0B;

        for (int ic = 0; ic < 64; ic++) {
            const float* si = s_in + ic * 612;
            #pragma unroll
            for (int ky = 0; ky < 3; ky++) {
                const float* r0 = si + (ty + ky) * 18 + tx;
                const float* r1 = r0 + 16 * 18;
                #pragma unroll
                for (int kx = 0; kx < 3; kx++) {
                    const float v0 = r0[kx];
                    const float v1 = r1[kx];
                    const int  k  = ic * 9 + ky * 3 + kx;
                    const float2 wA = s_wp[2 * k];
                    const float2 wB = s_wp[2 * k + 1];
                    p0A.x = fmaf(v0, wA.x, p0A.x); p0A.y = fmaf(v0, wA.y, p0A.y);
                    p0B.x = fmaf(v0, wB.x, p0B.x); p0B.y = fmaf(v0, wB.y, p0B.y);
                    p1A.x = fmaf(v1, wA.x, p1A.x); p1A.y = fmaf(v1, wA.y, p1A.y);
                    p1B.x = fmaf(v1, wB.x, p1B.x); p1B.y = fmaf(v1, wB.y, p1B.y);
                }
            }
        }

        const int oc = g29 * 4;
        const int o0 = ((b * PCH + oc) * HW) + (y0 + ty) * WW + (x0 + tx);
        const int o1 = o0 + 16 * WW;
        g_p[o0         ] = p0A.x;
        g_p[o0 +     HW] = p0A.y;
        g_p[o0 + 2 * HW] = p0B.x;
        g_p[o0 + 3 * HW] = p0B.y;
        g_p[o1         ] = p1A.x;
        g_p[o1 +     HW] = p1A.y;
        g_p[o1 + 2 * HW] = p1B.x;
        g_p[o1 + 3 * HW] = p1B.y;
        __syncthreads();
    }
}

// =========================================================================
// spline: per element (b,c,y,x): read 29 params from g_p, compute z + lad,
// block-reduce lad into g_partial (deterministic, no atomics).
// =========================================================================
__device__ __forceinline__ float softplusf(float t) {
    return fmaxf(t, 0.f) + log1pf(expf(-fabsf(t)));
}

__global__ void __launch_bounds__(256) spline_kernel(
    const float* __restrict__ xin,
    float* __restrict__ out)
{
    const int yrow = blockIdx.x;
    const int c    = blockIdx.y;
    const int b    = blockIdx.z;
    const int xcol = threadIdx.x;
    const int pix  = yrow * WW + xcol;

    const int pbase = ((b * PCH + c * 29) * HW) + pix;
    float pv[29];
    #pragma unroll
    for (int j = 0; j < 29; j++) pv[j] = g_p[pbase + j * HW];

    const float xv = xin[((b * C_ + c) * HW) + pix];

    // ---- widths: softmax -> min-bin -> cumsum -> knots ----
    float uw[10];
    #pragma unroll
    for (int j = 0; j < 10; j++) uw[j] = pv[j] * 0.125f;
    float mw = uw[0];
    #pragma unroll
    for (int j = 1; j < 10; j++) mw = fmaxf(mw, uw[j]);
    float ew[10]; float ssum = 0.f;
    #pragma unroll
    for (int j = 0; j < 10; j++) { ew[j] = expf(uw[j] - mw); ssum += ew[j]; }
    float inv = 1.0f / ssum;
    float cw[11]; cw[0] = -1.f;
    {
        float acc = 0.f;
        #pragma unroll
        for (int j = 0; j < 10; j++) {
            float wj = fmaf(0.99f * inv, ew[j], 0.001f);
            acc += wj;
            cw[j + 1] = fmaf(2.f, acc, -1.f);
        }
    }
    cw[10] = 1.f;
    float wd[10];
    #pragma unroll
    for (int j = 0; j < 10; j++) wd[j] = cw[j + 1] - cw[j];

    // ---- heights ----
    float uh[10];
    #pragma unroll
    for (int j = 0; j < 10; j++) uh[j] = pv[10 + j] * 0.125f;
    float mh = uh[0];
    #pragma unroll
    for (int j = 1; j < 10; j++) mh = fmaxf(mh, uh[j]);
    float eh[10]; float hsum = 0.f;
    #pragma unroll
    for (int j = 0; j < 10; j++) { eh[j] = expf(uh[j] - mh); hsum += eh[j]; }
    float hinv = 1.0f / hsum;
    float ch[11]; ch[0] = -1.f;
    {
        float acc = 0.f;
        #pragma unroll
        for (int j = 0; j < 10; j++) {
            float hj = fmaf(0.99f * hinv, eh[j], 0.001f);
            acc += hj;
            ch[j + 1] = fmaf(2.f, acc, -1.f);
        }
    }
    ch[10] = 1.f;
    float hd[10];
    #pragma unroll
    for (int j = 0; j < 10; j++) hd[j] = ch[j + 1] - ch[j];

    // ---- derivatives (padded with const so boundary deriv == 1) ----
    const float spc = 0.53974215f;          // log(exp(0.999)-1)
    const float dvE = 0.001f + softplusf(spc);
    float dv[11];
    dv[0] = dvE; dv[10] = dvE;
    #pragma unroll
    for (int j = 1; j < 10; j++) dv[j] = 0.001f + softplusf(pv[19 + j]);

    // ---- bin select via predicated scan (idx in [0,9]) ----
    const float xc = fminf(fmaxf(xv, -1.f), 1.f);
    float icw = cw[0], ibw = wd[0], ich = ch[0], ihh = hd[0], d0 = dv[0], d1 = dv[1];
    #pragma unroll
    for (int k = 1; k < 10; k++) {
        if (xc >= cw[k]) {
            icw = cw[k]; ibw = wd[k]; ich = ch[k]; ihh = hd[k];
            d0 = dv[k]; d1 = dv[k + 1];
        }
    }

    const float idl   = ihh / ibw;
    const float theta = (xc - icw) / ibw;
    const float th2   = theta * theta;
    const float tt    = theta * (1.f - theta);
    const float numer = ihh * (idl * th2 + d0 * tt);
    const float denom = idl + (d0 + d1 - 2.f * idl) * tt;
    const float zin   = ich + numer / denom;
    const float omt   = 1.f - theta;
    const float dnum  = idl * idl * (d1 * th2 + 2.f * idl * tt + d0 * omt * omt);
    const float ladv  = logf(dnum) - 2.f * logf(denom);

    const bool inside = (xv >= -1.f) && (xv <= 1.f);
    const float z = inside ? zin : xv;
    float l       = inside ? ladv : 0.f;

    out[((b * C_ + c) * HW) + pix] = z;

    // deterministic block reduction of l
    #pragma unroll
    for (int off = 16; off; off >>= 1)
        l += __shfl_down_sync(0xffffffffu, l, off);
    __shared__ float wr[8];
    const int wid = threadIdx.x >> 5, lane = threadIdx.x & 31;
    if (lane == 0) wr[wid] = l;
    __syncthreads();
    if (threadIdx.x == 0) {
        float s = 0.f;
        #pragma unroll
        for (int i = 0; i < 8; i++) s += wr[i];
        g_partial[(b * C_ + c) * HH + yrow] = s;
    }
}

// =========================================================================
// deterministic double-precision reduction of partials -> logabsdet[b]
// =========================================================================
__global__ void __launch_bounds__(256) reduce_kernel(float* __restrict__ out)
{
    const int b = blockIdx.x;
    const int tid = threadIdx.x;
    __shared__ double sd[256];
    double s = 0.0;
    #pragma unroll
    for (int i = 0; i < 4; i++)
        s += (double)g_partial[b * 1024 + tid + i * 256];
    sd[tid] = s;
    __syncthreads();
    for (int off = 128; off; off >>= 1) {
        if (tid < off) sd[tid] += sd[tid + off];
        __syncthreads();
    }
    if (tid == 0) out[B_ * C_ * HW + b] = (float)sd[0];
}

// =========================================================================
extern "C" void kernel_launch(void* const* d_in, const int* in_sizes, int n_in,
                              void* d_out, int out_size)
{
    const float* x     = (const float*)d_in[0];
    const float* clean = (const float*)d_in[1];
    const float* W1    = (const float*)d_in[2];
    const float* b1    = (const float*)d_in[3];
    const float* W2    = (const float*)d_in[4];
    const float* b2    = (const float*)d_in[5];
    float* out = (float*)d_out;

    cudaFuncSetAttribute(conv2_kernel,
                         cudaFuncAttributeMaxDynamicSharedMemorySize, SMEM2);

    conv1_kernel<<<dim3(256, 16, 16), 256>>>(clean, W1, b1);
    conv2_kernel<<<dim3(16, 8, 16), 256, SMEM2>>>(W2, b2);
    spline_kernel<<<dim3(256, 4, 16), 256>>>(x, out);
    reduce_kernel<<<16, 256>>>(out);
}

// round 2
// speedup vs baseline: 1.1738x; 1.1738x over previous
#include <cuda_runtime.h>
#include <cstdint>

#define B_   16
#define C_   4
#define HH   256
#define WW   256
#define HID  64
#define PCH  116          // C_*(3*10-1)
#define HW   (HH*WW)      // 65536

// ---------------- device scratch (no allocations allowed) ----------------
__device__ float g_hid[B_ * HID * HW];        // 268 MB
__device__ float g_p  [B_ * PCH * HW];        // 486 MB
__device__ float g_partial[B_ * C_ * HH];     // 16384 partial lad sums

// ---------------- packed fp32x2 helpers (sm_103a FFMA2) -------------------
__device__ __forceinline__ void fma2(uint64_t& acc, uint64_t a, uint64_t b) {
    asm("fma.rn.f32x2 %0, %1, %2, %0;" : "+l"(acc) : "l"(a), "l"(b));
}
__device__ __forceinline__ uint64_t pack2(float lo, float hi) {
    uint64_t r; asm("mov.b64 %0, {%1,%2};" : "=l"(r) : "f"(lo), "f"(hi)); return r;
}
__device__ __forceinline__ float2 unpack2(uint64_t v) {
    float2 r; asm("mov.b64 {%0,%1}, %2;" : "=f"(r.x), "=f"(r.y) : "l"(v)); return r;
}

// =========================================================================
// conv1: clean[16,4,256,256] -> relu(conv3x3) -> g_hid[16,64,256,256]
// =========================================================================
__global__ void __launch_bounds__(256) conv1_kernel(
    const float* __restrict__ clean,
    const float* __restrict__ W1,
    const float* __restrict__ b1)
{
    __shared__ float2 s_wp[36 * 2];
    __shared__ float  s_b[4];

    const int y = blockIdx.x;
    const int g = blockIdx.y;
    const int b = blockIdx.z;
    const int tid = threadIdx.x;

    if (tid < 72) {
        int k = tid >> 1, half = tid & 1;
        int oc0 = g * 4 + 2 * half;
        s_wp[2 * k + half] = make_float2(W1[oc0 * 36 + k], W1[(oc0 + 1) * 36 + k]);
    }
    if (tid < 4) s_b[tid] = b1[g * 4 + tid];
    __syncthreads();

    float2 aA = make_float2(s_b[0], s_b[1]);
    float2 aB = make_float2(s_b[2], s_b[3]);

    #pragma unroll
    for (int ic = 0; ic < 4; ic++) {
        #pragma unroll
        for (int ky = 0; ky < 3; ky++) {
            const int yy = y + ky - 1;
            const bool yok = ((unsigned)yy < 256u);
            #pragma unroll
            for (int kx = 0; kx < 3; kx++) {
                const int xx = tid + kx - 1;
                float v = 0.f;
                if (yok && (unsigned)xx < 256u)
                    v = clean[((b * 4 + ic) * HW) + yy * WW + xx];
                const int k = ic * 9 + ky * 3 + kx;
                float2 wA = s_wp[2 * k], wB = s_wp[2 * k + 1];
                aA.x = fmaf(v, wA.x, aA.x); aA.y = fmaf(v, wA.y, aA.y);
                aB.x = fmaf(v, wB.x, aB.x); aB.y = fmaf(v, wB.y, aB.y);
            }
        }
    }
    const int o = ((b * HID + g * 4) * HW) + y * WW + tid;
    g_hid[o         ] = fmaxf(aA.x, 0.f);
    g_hid[o +     HW] = fmaxf(aA.y, 0.f);
    g_hid[o + 2 * HW] = fmaxf(aB.x, 0.f);
    g_hid[o + 3 * HW] = fmaxf(aB.y, 0.f);
}

// =========================================================================
// conv2 (FFMA2): g_hid -> g_p[16,116,256,256]
// Tile 32(x) x 16(y), 128 threads. Thread: 4 consecutive x (2 packed pairs)
// x 8 output channels. Weights duplicated (w,w) in smem, broadcast LDS.128.
// 15 passes of 8 oc (116 padded to 120 with guards).
// =========================================================================
#define SIN_ROW  36
#define SIN_IC   (18 * SIN_ROW)          // 648 floats per ic
#define SIN_FL   (64 * SIN_IC)           // 41472 floats
#define SWD_N    (576 * 8)               // 4608 dup-pairs (u64)
#define SMEM2    (SIN_FL * 4 + SWD_N * 8)  // 202,752 bytes

__global__ void __launch_bounds__(128) conv2_kernel(
    const float* __restrict__ W2,
    const float* __restrict__ b2)
{
    extern __shared__ float smem[];
    float*    s_in = smem;                         // [ic][r 0..17][c 0..35]
    uint64_t* s_wd = (uint64_t*)(smem + SIN_FL);   // [k][oc8] duplicated

    const int x0g = blockIdx.x * 32;
    const int y0  = blockIdx.y * 16;
    const int b   = blockIdx.z;
    const int tid = threadIdx.x;

    // ---- load input tile with zero-padded halo ----
    #pragma unroll 4
    for (int i = tid; i < SIN_FL; i += 128) {
        const int ic = i / SIN_IC;
        const int rem = i - ic * SIN_IC;
        const int r  = rem / SIN_ROW;
        const int c  = rem - r * SIN_ROW;
        const int yy = y0 + r - 1;
        const int xx = x0g + c - 1;
        float v = 0.f;
        if (c < 34 && (unsigned)yy < 256u && (unsigned)xx < 256u)
            v = g_hid[((b * HID + ic) * HW) + yy * WW + xx];
        s_in[i] = v;
    }

    const int xt  = tid & 7;
    const int yt  = tid >> 3;       // 0..15
    const int lx0 = xt * 4;

    for (int pass = 0; pass < 15; ++pass) {
        const int ocb = pass * 8;

        __syncthreads();   // previous pass finished reading s_wd
        // ---- load duplicated weights: lane-mapped conflict-free stores ----
        #pragma unroll 4
        for (int i = tid; i < SWD_N; i += 128) {
            const int oc8 = i & 7;
            const int k   = i >> 3;
            const int oc  = ocb + oc8;
            const float w = (oc < PCH) ? W2[oc * 576 + k] : 0.f;
            s_wd[i] = pack2(w, w);
        }
        __syncthreads();

        uint64_t acc[8][2];
        #pragma unroll
        for (int oc8 = 0; oc8 < 8; ++oc8) {
            const int oc = ocb + oc8;
            const float bv = (oc < PCH) ? b2[oc] : 0.f;
            acc[oc8][0] = pack2(bv, bv);
            acc[oc8][1] = pack2(bv, bv);
        }

        for (int ic = 0; ic < 64; ++ic) {
            const float* rowb = s_in + ic * SIN_IC + yt * SIN_ROW + lx0;
            #pragma unroll
            for (int ky = 0; ky < 3; ++ky) {
                const float* p = rowb + ky * SIN_ROW;
                const float4 v03 = *(const float4*)p;
                const float2 v45 = *(const float2*)(p + 4);
                uint64_t P01 = pack2(v03.x, v03.y);
                uint64_t P12 = pack2(v03.y, v03.z);
                uint64_t P23 = pack2(v03.z, v03.w);
                uint64_t P34 = pack2(v03.w, v45.x);
                uint64_t P45 = pack2(v45.x, v45.y);
                uint64_t a0[3] = {P01, P12, P23};
                uint64_t a1[3] = {P23, P34, P45};
                const ulonglong2* wq =
                    (const ulonglong2*)(s_wd + (ic * 9 + ky * 3) * 8);
                #pragma unroll
                for (int kx = 0; kx < 3; ++kx) {
                    const ulonglong2 w01 = wq[kx * 4 + 0];
                    const ulonglong2 w23 = wq[kx * 4 + 1];
                    const ulonglong2 w45 = wq[kx * 4 + 2];
                    const ulonglong2 w67 = wq[kx * 4 + 3];
                    fma2(acc[0][0], a0[kx], w01.x); fma2(acc[0][1], a1[kx], w01.x);
                    fma2(acc[1][0], a0[kx], w01.y); fma2(acc[1][1], a1[kx], w01.y);
                    fma2(acc[2][0], a0[kx], w23.x); fma2(acc[2][1], a1[kx], w23.x);
                    fma2(acc[3][0], a0[kx], w23.y); fma2(acc[3][1], a1[kx], w23.y);
                    fma2(acc[4][0], a0[kx], w45.x); fma2(acc[4][1], a1[kx], w45.x);
                    fma2(acc[5][0], a0[kx], w45.y); fma2(acc[5][1], a1[kx], w45.y);
                    fma2(acc[6][0], a0[kx], w67.x); fma2(acc[6][1], a1[kx], w67.x);
                    fma2(acc[7][0], a0[kx], w67.y); fma2(acc[7][1], a1[kx], w67.y);
                }
            }
        }

        // ---- store 8 oc x 4 px ----
        const int y = y0 + yt;
        #pragma unroll
        for (int oc8 = 0; oc8 < 8; ++oc8) {
            const int oc = ocb + oc8;
            if (oc < PCH) {
                const float2 lo = unpack2(acc[oc8][0]);
                const float2 hi = unpack2(acc[oc8][1]);
                float4 o4 = make_float4(lo.x, lo.y, hi.x, hi.y);
                *(float4*)&g_p[((b * PCH + oc) * HW) + y * WW + x0g + lx0] = o4;
            }
        }
    }
}

// =========================================================================
// spline: per element compute z + lad; block-reduce lad (deterministic).
// =========================================================================
__device__ __forceinline__ float softplusf(float t) {
    return fmaxf(t, 0.f) + log1pf(expf(-fabsf(t)));
}

__global__ void __launch_bounds__(256) spline_kernel(
    const float* __restrict__ xin,
    float* __restrict__ out)
{
    const int yrow = blockIdx.x;
    const int c    = blockIdx.y;
    const int b    = blockIdx.z;
    const int xcol = threadIdx.x;
    const int pix  = yrow * WW + xcol;

    const int pbase = ((b * PCH + c * 29) * HW) + pix;
    float pv[29];
    #pragma unroll
    for (int j = 0; j < 29; j++) pv[j] = g_p[pbase + j * HW];

    const float xv = xin[((b * C_ + c) * HW) + pix];

    float uw[10];
    #pragma unroll
    for (int j = 0; j < 10; j++) uw[j] = pv[j] * 0.125f;
    float mw = uw[0];
    #pragma unroll
    for (int j = 1; j < 10; j++) mw = fmaxf(mw, uw[j]);
    float ew[10]; float ssum = 0.f;
    #pragma unroll
    for (int j = 0; j < 10; j++) { ew[j] = expf(uw[j] - mw); ssum += ew[j]; }
    float inv = 1.0f / ssum;
    float cw[11]; cw[0] = -1.f;
    {
        float acc = 0.f;
        #pragma unroll
        for (int j = 0; j < 10; j++) {
            float wj = fmaf(0.99f * inv, ew[j], 0.001f);
            acc += wj;
            cw[j + 1] = fmaf(2.f, acc, -1.f);
        }
    }
    cw[10] = 1.f;
    float wd[10];
    #pragma unroll
    for (int j = 0; j < 10; j++) wd[j] = cw[j + 1] - cw[j];

    float uh[10];
    #pragma unroll
    for (int j = 0; j < 10; j++) uh[j] = pv[10 + j] * 0.125f;
    float mh = uh[0];
    #pragma unroll
    for (int j = 1; j < 10; j++) mh = fmaxf(mh, uh[j]);
    float eh[10]; float hsum = 0.f;
    #pragma unroll
    for (int j = 0; j < 10; j++) { eh[j] = expf(uh[j] - mh); hsum += eh[j]; }
    float hinv = 1.0f / hsum;
    float ch[11]; ch[0] = -1.f;
    {
        float acc = 0.f;
        #pragma unroll
        for (int j = 0; j < 10; j++) {
            float hj = fmaf(0.99f * hinv, eh[j], 0.001f);
            acc += hj;
            ch[j + 1] = fmaf(2.f, acc, -1.f);
        }
    }
    ch[10] = 1.f;
    float hd[10];
    #pragma unroll
    for (int j = 0; j < 10; j++) hd[j] = ch[j + 1] - ch[j];

    const float spc = 0.53974215f;
    const float dvE = 0.001f + softplusf(spc);
    float dv[11];
    dv[0] = dvE; dv[10] = dvE;
    #pragma unroll
    for (int j = 1; j < 10; j++) dv[j] = 0.001f + softplusf(pv[19 + j]);

    const float xc = fminf(fmaxf(xv, -1.f), 1.f);
    float icw = cw[0], ibw = wd[0], ich = ch[0], ihh = hd[0], d0 = dv[0], d1 = dv[1];
    #pragma unroll
    for (int k = 1; k < 10; k++) {
        if (xc >= cw[k]) {
            icw = cw[k]; ibw = wd[k]; ich = ch[k]; ihh = hd[k];
            d0 = dv[k]; d1 = dv[k + 1];
        }
    }

    const float idl   = ihh / ibw;
    const float theta = (xc - icw) / ibw;
    const float th2   = theta * theta;
    const float tt    = theta * (1.f - theta);
    const float numer = ihh * (idl * th2 + d0 * tt);
    const float denom = idl + (d0 + d1 - 2.f * idl) * tt;
    const float zin   = ich + numer / denom;
    const float omt   = 1.f - theta;
    const float dnum  = idl * idl * (d1 * th2 + 2.f * idl * tt + d0 * omt * omt);
    const float ladv  = logf(dnum) - 2.f * logf(denom);

    const bool inside = (xv >= -1.f) && (xv <= 1.f);
    const float z = inside ? zin : xv;
    float l       = inside ? ladv : 0.f;

    out[((b * C_ + c) * HW) + pix] = z;

    #pragma unroll
    for (int off = 16; off; off >>= 1)
        l += __shfl_down_sync(0xffffffffu, l, off);
    __shared__ float wr[8];
    const int wid = threadIdx.x >> 5, lane = threadIdx.x & 31;
    if (lane == 0) wr[wid] = l;
    __syncthreads();
    if (threadIdx.x == 0) {
        float s = 0.f;
        #pragma unroll
        for (int i = 0; i < 8; i++) s += wr[i];
        g_partial[(b * C_ + c) * HH + yrow] = s;
    }
}

// =========================================================================
__global__ void __launch_bounds__(256) reduce_kernel(float* __restrict__ out)
{
    const int b = blockIdx.x;
    const int tid = threadIdx.x;
    __shared__ double sd[256];
    double s = 0.0;
    #pragma unroll
    for (int i = 0; i < 4; i++)
        s += (double)g_partial[b * 1024 + tid + i * 256];
    sd[tid] = s;
    __syncthreads();
    for (int off = 128; off; off >>= 1) {
        if (tid < off) sd[tid] += sd[tid + off];
        __syncthreads();
    }
    if (tid == 0) out[B_ * C_ * HW + b] = (float)sd[0];
}

// =========================================================================
extern "C" void kernel_launch(void* const* d_in, const int* in_sizes, int n_in,
                              void* d_out, int out_size)
{
    const float* x     = (const float*)d_in[0];
    const float* clean = (const float*)d_in[1];
    const float* W1    = (const float*)d_in[2];
    const float* b1    = (const float*)d_in[3];
    const float* W2    = (const float*)d_in[4];
    const float* b2    = (const float*)d_in[5];
    float* out = (float*)d_out;

    cudaFuncSetAttribute(conv2_kernel,
                         cudaFuncAttributeMaxDynamicSharedMemorySize, SMEM2);

    conv1_kernel<<<dim3(256, 16, 16), 256>>>(clean, W1, b1);
    conv2_kernel<<<dim3(8, 16, 16), 128, SMEM2>>>(W2, b2);
    spline_kernel<<<dim3(256, 4, 16), 256>>>(x, out);
    reduce_kernel<<<16, 256>>>(out);
}

// round 3
// speedup vs baseline: 1.3296x; 1.1327x over previous
#include <cuda_runtime.h>
#include <cstdint>

#define B_   16
#define C_   4
#define HH   256
#define WW   256
#define HID  64
#define PCH  116          // C_*(3*10-1)
#define HW   (HH*WW)      // 65536

// ---------------- device scratch (no allocations allowed) ----------------
__device__ float g_hid[B_ * HID * HW];        // 268 MB
__device__ float g_p  [B_ * PCH * HW];        // 486 MB
__device__ float g_partial[B_ * C_ * HH];     // 16384 partial lad sums

// ---------------- packed fp32x2 helpers (sm_103a FFMA2) -------------------
__device__ __forceinline__ void fma2(uint64_t& acc, uint64_t a, uint64_t b) {
    asm("fma.rn.f32x2 %0, %1, %2, %0;" : "+l"(acc) : "l"(a), "l"(b));
}
__device__ __forceinline__ uint64_t pack2(float lo, float hi) {
    uint64_t r; asm("mov.b64 %0, {%1,%2};" : "=l"(r) : "f"(lo), "f"(hi)); return r;
}
__device__ __forceinline__ float2 unpack2(uint64_t v) {
    float2 r; asm("mov.b64 {%0,%1}, %2;" : "=f"(r.x), "=f"(r.y) : "l"(v)); return r;
}

// =========================================================================
// conv1: clean[16,4,256,256] -> relu(conv3x3) -> g_hid[16,64,256,256]
// =========================================================================
__global__ void __launch_bounds__(256) conv1_kernel(
    const float* __restrict__ clean,
    const float* __restrict__ W1,
    const float* __restrict__ b1)
{
    __shared__ float2 s_wp[36 * 2];
    __shared__ float  s_b[4];

    const int y = blockIdx.x;
    const int g = blockIdx.y;
    const int b = blockIdx.z;
    const int tid = threadIdx.x;

    if (tid < 72) {
        int k = tid >> 1, half = tid & 1;
        int oc0 = g * 4 + 2 * half;
        s_wp[2 * k + half] = make_float2(W1[oc0 * 36 + k], W1[(oc0 + 1) * 36 + k]);
    }
    if (tid < 4) s_b[tid] = b1[g * 4 + tid];
    __syncthreads();

    float2 aA = make_float2(s_b[0], s_b[1]);
    float2 aB = make_float2(s_b[2], s_b[3]);

    #pragma unroll
    for (int ic = 0; ic < 4; ic++) {
        #pragma unroll
        for (int ky = 0; ky < 3; ky++) {
            const int yy = y + ky - 1;
            const bool yok = ((unsigned)yy < 256u);
            #pragma unroll
            for (int kx = 0; kx < 3; kx++) {
                const int xx = tid + kx - 1;
                float v = 0.f;
                if (yok && (unsigned)xx < 256u)
                    v = clean[((b * 4 + ic) * HW) + yy * WW + xx];
                const int k = ic * 9 + ky * 3 + kx;
                float2 wA = s_wp[2 * k], wB = s_wp[2 * k + 1];
                aA.x = fmaf(v, wA.x, aA.x); aA.y = fmaf(v, wA.y, aA.y);
                aB.x = fmaf(v, wB.x, aB.x); aB.y = fmaf(v, wB.y, aB.y);
            }
        }
    }
    const int o = ((b * HID + g * 4) * HW) + y * WW + tid;
    g_hid[o         ] = fmaxf(aA.x, 0.f);
    g_hid[o +     HW] = fmaxf(aA.y, 0.f);
    g_hid[o + 2 * HW] = fmaxf(aB.x, 0.f);
    g_hid[o + 3 * HW] = fmaxf(aB.y, 0.f);
}

// =========================================================================
// conv2 (FFMA2): g_hid -> g_p[16,116,256,256]
// Tile 32(x) x 16(y), 256 threads (8 warps/SM = 2/SMSP for latency hiding).
// Thread: 1 pixel-pair (2 consecutive x) x 8 output channels.
// Weights duplicated (w,w) in smem, broadcast LDS.128. 15 passes of 8 oc.
// =========================================================================
#define SIN_ROW  36
#define SIN_IC   (18 * SIN_ROW)          // 648 floats per ic
#define SIN_FL   (64 * SIN_IC)           // 41472 floats
#define SWD_N    (576 * 8)               // 4608 dup-pairs (u64)
#define SMEM2    (SIN_FL * 4 + SWD_N * 8)  // 202,752 bytes

__global__ void __launch_bounds__(256) conv2_kernel(
    const float* __restrict__ W2,
    const float* __restrict__ b2)
{
    extern __shared__ float smem[];
    float*    s_in = smem;                         // [ic][r 0..17][c 0..35]
    uint64_t* s_wd = (uint64_t*)(smem + SIN_FL);   // [k][oc8] duplicated

    const int x0g = blockIdx.x * 32;
    const int y0  = blockIdx.y * 16;
    const int b   = blockIdx.z;
    const int tid = threadIdx.x;

    // ---- load input tile with zero-padded halo ----
    #pragma unroll 4
    for (int i = tid; i < SIN_FL; i += 256) {
        const int ic = i / SIN_IC;
        const int rem = i - ic * SIN_IC;
        const int r  = rem / SIN_ROW;
        const int c  = rem - r * SIN_ROW;
        const int yy = y0 + r - 1;
        const int xx = x0g + c - 1;
        float v = 0.f;
        if (c < 34 && (unsigned)yy < 256u && (unsigned)xx < 256u)
            v = g_hid[((b * HID + ic) * HW) + yy * WW + xx];
        s_in[i] = v;
    }

    const int tx  = tid & 15;       // pixel pair: x = x0g + 2*tx + {0,1}
    const int ty  = tid >> 4;       // row 0..15
    const int cb  = 2 * tx;         // s_in column base

    for (int pass = 0; pass < 15; ++pass) {
        const int ocb = pass * 8;

        __syncthreads();   // previous pass finished reading s_wd
        // ---- load duplicated weights (coalesced: consecutive k per warp) ----
        #pragma unroll 4
        for (int i = tid; i < SWD_N; i += 256) {
            const int oc8 = i / 576;
            const int k   = i - oc8 * 576;
            const int oc  = ocb + oc8;
            const float w = (oc < PCH) ? W2[oc * 576 + k] : 0.f;
            s_wd[k * 8 + oc8] = pack2(w, w);
        }
        __syncthreads();

        uint64_t acc[8];
        #pragma unroll
        for (int oc8 = 0; oc8 < 8; ++oc8) {
            const int oc = ocb + oc8;
            const float bv = (oc < PCH) ? b2[oc] : 0.f;
            acc[oc8] = pack2(bv, bv);
        }

        for (int ic = 0; ic < 64; ++ic) {
            const float* rowb = s_in + ic * SIN_IC + ty * SIN_ROW + cb;
            #pragma unroll
            for (int ky = 0; ky < 3; ++ky) {
                const float* p = rowb + ky * SIN_ROW;
                const float2 va = *(const float2*)p;
                const float2 vb = *(const float2*)(p + 2);
                uint64_t P0 = pack2(va.x, va.y);
                uint64_t P1 = pack2(va.y, vb.x);
                uint64_t P2 = pack2(vb.x, vb.y);
                uint64_t P[3] = {P0, P1, P2};
                const ulonglong2* wq =
                    (const ulonglong2*)(s_wd + (ic * 9 + ky * 3) * 8);
                #pragma unroll
                for (int kx = 0; kx < 3; ++kx) {
                    const ulonglong2 w01 = wq[kx * 4 + 0];
                    const ulonglong2 w23 = wq[kx * 4 + 1];
                    const ulonglong2 w45 = wq[kx * 4 + 2];
                    const ulonglong2 w67 = wq[kx * 4 + 3];
                    fma2(acc[0], P[kx], w01.x);
                    fma2(acc[1], P[kx], w01.y);
                    fma2(acc[2], P[kx], w23.x);
                    fma2(acc[3], P[kx], w23.y);
                    fma2(acc[4], P[kx], w45.x);
                    fma2(acc[5], P[kx], w45.y);
                    fma2(acc[6], P[kx], w67.x);
                    fma2(acc[7], P[kx], w67.y);
                }
            }
        }

        // ---- store 8 oc x 2 px (float2, coalesced) ----
        const int y = y0 + ty;
        #pragma unroll
        for (int oc8 = 0; oc8 < 8; ++oc8) {
            const int oc = ocb + oc8;
            if (oc < PCH) {
                const float2 v = unpack2(acc[oc8]);
                *(float2*)&g_p[((b * PCH + oc) * HW) + y * WW + x0g + cb] = v;
            }
        }
    }
}

// =========================================================================
// spline: per element compute z + lad; block-reduce lad (deterministic).
// =========================================================================
__device__ __forceinline__ float softplusf(float t) {
    return fmaxf(t, 0.f) + log1pf(expf(-fabsf(t)));
}

__global__ void __launch_bounds__(256) spline_kernel(
    const float* __restrict__ xin,
    float* __restrict__ out)
{
    const int yrow = blockIdx.x;
    const int c    = blockIdx.y;
    const int b    = blockIdx.z;
    const int xcol = threadIdx.x;
    const int pix  = yrow * WW + xcol;

    const int pbase = ((b * PCH + c * 29) * HW) + pix;
    float pv[29];
    #pragma unroll
    for (int j = 0; j < 29; j++) pv[j] = g_p[pbase + j * HW];

    const float xv = xin[((b * C_ + c) * HW) + pix];

    float uw[10];
    #pragma unroll
    for (int j = 0; j < 10; j++) uw[j] = pv[j] * 0.125f;
    float mw = uw[0];
    #pragma unroll
    for (int j = 1; j < 10; j++) mw = fmaxf(mw, uw[j]);
    float ew[10]; float ssum = 0.f;
    #pragma unroll
    for (int j = 0; j < 10; j++) { ew[j] = expf(uw[j] - mw); ssum += ew[j]; }
    float inv = 1.0f / ssum;
    float cw[11]; cw[0] = -1.f;
    {
        float acc = 0.f;
        #pragma unroll
        for (int j = 0; j < 10; j++) {
            float wj = fmaf(0.99f * inv, ew[j], 0.001f);
            acc += wj;
            cw[j + 1] = fmaf(2.f, acc, -1.f);
        }
    }
    cw[10] = 1.f;
    float wd[10];
    #pragma unroll
    for (int j = 0; j < 10; j++) wd[j] = cw[j + 1] - cw[j];

    float uh[10];
    #pragma unroll
    for (int j = 0; j < 10; j++) uh[j] = pv[10 + j] * 0.125f;
    float mh = uh[0];
    #pragma unroll
    for (int j = 1; j < 10; j++) mh = fmaxf(mh, uh[j]);
    float eh[10]; float hsum = 0.f;
    #pragma unroll
    for (int j = 0; j < 10; j++) { eh[j] = expf(uh[j] - mh); hsum += eh[j]; }
    float hinv = 1.0f / hsum;
    float ch[11]; ch[0] = -1.f;
    {
        float acc = 0.f;
        #pragma unroll
        for (int j = 0; j < 10; j++) {
            float hj = fmaf(0.99f * hinv, eh[j], 0.001f);
            acc += hj;
            ch[j + 1] = fmaf(2.f, acc, -1.f);
        }
    }
    ch[10] = 1.f;
    float hd[10];
    #pragma unroll
    for (int j = 0; j < 10; j++) hd[j] = ch[j + 1] - ch[j];

    const float spc = 0.53974215f;
    const float dvE = 0.001f + softplusf(spc);
    float dv[11];
    dv[0] = dvE; dv[10] = dvE;
    #pragma unroll
    for (int j = 1; j < 10; j++) dv[j] = 0.001f + softplusf(pv[19 + j]);

    const float xc = fminf(fmaxf(xv, -1.f), 1.f);
    float icw = cw[0], ibw = wd[0], ich = ch[0], ihh = hd[0], d0 = dv[0], d1 = dv[1];
    #pragma unroll
    for (int k = 1; k < 10; k++) {
        if (xc >= cw[k]) {
            icw = cw[k]; ibw = wd[k]; ich = ch[k]; ihh = hd[k];
            d0 = dv[k]; d1 = dv[k + 1];
        }
    }

    const float idl   = ihh / ibw;
    const float theta = (xc - icw) / ibw;
    const float th2   = theta * theta;
    const float tt    = theta * (1.f - theta);
    const float numer = ihh * (idl * th2 + d0 * tt);
    const float denom = idl + (d0 + d1 - 2.f * idl) * tt;
    const float zin   = ich + numer / denom;
    const float omt   = 1.f - theta;
    const float dnum  = idl * idl * (d1 * th2 + 2.f * idl * tt + d0 * omt * omt);
    const float ladv  = logf(dnum) - 2.f * logf(denom);

    const bool inside = (xv >= -1.f) && (xv <= 1.f);
    const float z = inside ? zin : xv;
    float l       = inside ? ladv : 0.f;

    out[((b * C_ + c) * HW) + pix] = z;

    #pragma unroll
    for (int off = 16; off; off >>= 1)
        l += __shfl_down_sync(0xffffffffu, l, off);
    __shared__ float wr[8];
    const int wid = threadIdx.x >> 5, lane = threadIdx.x & 31;
    if (lane == 0) wr[wid] = l;
    __syncthreads();
    if (threadIdx.x == 0) {
        float s = 0.f;
        #pragma unroll
        for (int i = 0; i < 8; i++) s += wr[i];
        g_partial[(b * C_ + c) * HH + yrow] = s;
    }
}

// =========================================================================
__global__ void __launch_bounds__(256) reduce_kernel(float* __restrict__ out)
{
    const int b = blockIdx.x;
    const int tid = threadIdx.x;
    __shared__ double sd[256];
    double s = 0.0;
    #pragma unroll
    for (int i = 0; i < 4; i++)
        s += (double)g_partial[b * 1024 + tid + i * 256];
    sd[tid] = s;
    __syncthreads();
    for (int off = 128; off; off >>= 1) {
        if (tid < off) sd[tid] += sd[tid + off];
        __syncthreads();
    }
    if (tid == 0) out[B_ * C_ * HW + b] = (float)sd[0];
}

// =========================================================================
extern "C" void kernel_launch(void* const* d_in, const int* in_sizes, int n_in,
                              void* d_out, int out_size)
{
    const float* x     = (const float*)d_in[0];
    const float* clean = (const float*)d_in[1];
    const float* W1    = (const float*)d_in[2];
    const float* b1    = (const float*)d_in[3];
    const float* W2    = (const float*)d_in[4];
    const float* b2    = (const float*)d_in[5];
    float* out = (float*)d_out;

    cudaFuncSetAttribute(conv2_kernel,
                         cudaFuncAttributeMaxDynamicSharedMemorySize, SMEM2);

    conv1_kernel<<<dim3(256, 16, 16), 256>>>(clean, W1, b1);
    conv2_kernel<<<dim3(8, 16, 16), 256, SMEM2>>>(W2, b2);
    spline_kernel<<<dim3(256, 4, 16), 256>>>(x, out);
    reduce_kernel<<<16, 256>>>(out);
}

// round 4
// speedup vs baseline: 1.6031x; 1.2057x over previous
#include <cuda_runtime.h>
#include <cstdint>

#define B_   16
#define C_   4
#define HH   256
#define WW   256
#define HID  64
#define PCH  116          // C_*(3*10-1)
#define HW   (HH*WW)      // 65536

// ---------------- device scratch (no allocations allowed) ----------------
__device__ float g_hid[B_ * HID * HW];        // 268 MB
__device__ float g_p  [B_ * PCH * HW];        // 486 MB
__device__ float g_partial[B_ * C_ * HH];     // 16384 partial lad sums

// ---------------- packed fp32x2 helpers (sm_103a FFMA2) -------------------
__device__ __forceinline__ void fma2(uint64_t& acc, uint64_t a, uint64_t b) {
    asm("fma.rn.f32x2 %0, %1, %2, %0;" : "+l"(acc) : "l"(a), "l"(b));
}
__device__ __forceinline__ uint64_t pack2(float lo, float hi) {
    uint64_t r; asm("mov.b64 %0, {%1,%2};" : "=l"(r) : "f"(lo), "f"(hi)); return r;
}
__device__ __forceinline__ float2 unpack2(uint64_t v) {
    float2 r; asm("mov.b64 {%0,%1}, %2;" : "=f"(r.x), "=f"(r.y) : "l"(v)); return r;
}

// =========================================================================
// conv1: clean[16,4,256,256] -> relu(conv3x3) -> g_hid[16,64,256,256]
// =========================================================================
__global__ void __launch_bounds__(256) conv1_kernel(
    const float* __restrict__ clean,
    const float* __restrict__ W1,
    const float* __restrict__ b1)
{
    __shared__ float2 s_wp[36 * 2];
    __shared__ float  s_b[4];

    const int y = blockIdx.x;
    const int g = blockIdx.y;
    const int b = blockIdx.z;
    const int tid = threadIdx.x;

    if (tid < 72) {
        int k = tid >> 1, half = tid & 1;
        int oc0 = g * 4 + 2 * half;
        s_wp[2 * k + half] = make_float2(W1[oc0 * 36 + k], W1[(oc0 + 1) * 36 + k]);
    }
    if (tid < 4) s_b[tid] = b1[g * 4 + tid];
    __syncthreads();

    float2 aA = make_float2(s_b[0], s_b[1]);
    float2 aB = make_float2(s_b[2], s_b[3]);

    #pragma unroll
    for (int ic = 0; ic < 4; ic++) {
        #pragma unroll
        for (int ky = 0; ky < 3; ky++) {
            const int yy = y + ky - 1;
            const bool yok = ((unsigned)yy < 256u);
            #pragma unroll
            for (int kx = 0; kx < 3; kx++) {
                const int xx = tid + kx - 1;
                float v = 0.f;
                if (yok && (unsigned)xx < 256u)
                    v = clean[((b * 4 + ic) * HW) + yy * WW + xx];
                const int k = ic * 9 + ky * 3 + kx;
                float2 wA = s_wp[2 * k], wB = s_wp[2 * k + 1];
                aA.x = fmaf(v, wA.x, aA.x); aA.y = fmaf(v, wA.y, aA.y);
                aB.x = fmaf(v, wB.x, aB.x); aB.y = fmaf(v, wB.y, aB.y);
            }
        }
    }
    const int o = ((b * HID + g * 4) * HW) + y * WW + tid;
    g_hid[o         ] = fmaxf(aA.x, 0.f);
    g_hid[o +     HW] = fmaxf(aA.y, 0.f);
    g_hid[o + 2 * HW] = fmaxf(aB.x, 0.f);
    g_hid[o + 3 * HW] = fmaxf(aB.y, 0.f);
}

// =========================================================================
// conv2 (FFMA2, K-split): g_hid -> g_p[16,116,256,256]
// Tile 32(x) x 32(y), 256 threads, 2 phases of 32 ic each.
// Thread: 2 y-pixels (ty, ty+16) x 1 x-pair x 8 oc -> 16 packed accums.
// Phase A (icbase=0): g_p = bias + partial. Phase B (icbase=32): g_p +=.
// =========================================================================
#define SIN_ROW2  36
#define SIN_IC2   (34 * SIN_ROW2)          // 1224 floats per ic
#define SIN_FL2   (32 * SIN_IC2)           // 39168 floats (156.7 KB)
#define SWD_N2    (288 * 8)                // 2304 dup-pairs (u64, 18.4 KB)
#define SMEM2     (SIN_FL2 * 4 + SWD_N2 * 8)   // 175,104 bytes

__global__ void __launch_bounds__(256) conv2_kernel(
    const float* __restrict__ W2,
    const float* __restrict__ b2,
    const int icbase, const int accumulate)
{
    extern __shared__ float smem[];
    float*    s_in = smem;                          // [ic32][r 0..33][c 0..35]
    uint64_t* s_wd = (uint64_t*)(smem + SIN_FL2);   // [k(288)][oc8] duplicated

    const int x0g = blockIdx.x * 32;
    const int y0  = blockIdx.y * 32;
    const int b   = blockIdx.z;
    const int tid = threadIdx.x;

    // ---- load input tile (32 ic, zero-padded halo) ----
    #pragma unroll 4
    for (int i = tid; i < SIN_FL2; i += 256) {
        const int icl = i / SIN_IC2;
        const int rem = i - icl * SIN_IC2;
        const int r  = rem / SIN_ROW2;
        const int c  = rem - r * SIN_ROW2;
        const int yy = y0 + r - 1;
        const int xx = x0g + c - 1;
        float v = 0.f;
        if (c < 34 && (unsigned)yy < 256u && (unsigned)xx < 256u)
            v = g_hid[((b * HID + icbase + icl) * HW) + yy * WW + xx];
        s_in[i] = v;
    }

    const int tx  = tid & 15;       // x-pair: x = x0g + 2*tx + {0,1}
    const int ty  = tid >> 4;       // 0..15 ; rows y0+ty and y0+ty+16
    const int cb  = 2 * tx;

    for (int pass = 0; pass < 15; ++pass) {
        const int ocb = pass * 8;

        __syncthreads();   // previous pass finished reading s_wd
        // ---- load duplicated weights (coalesced: consecutive k per warp) ----
        #pragma unroll 3
        for (int i = tid; i < SWD_N2; i += 256) {
            const int oc8 = i / 288;
            const int k   = i - oc8 * 288;
            const int oc  = ocb + oc8;
            const float w = (oc < PCH) ? W2[oc * 576 + icbase * 9 + k] : 0.f;
            s_wd[k * 8 + oc8] = pack2(w, w);
        }
        __syncthreads();

        uint64_t acc0[8], acc1[8];
        #pragma unroll
        for (int oc8 = 0; oc8 < 8; ++oc8) {
            const int oc = ocb + oc8;
            const float bv = (!accumulate && oc < PCH) ? b2[oc] : 0.f;
            acc0[oc8] = pack2(bv, bv);
            acc1[oc8] = pack2(bv, bv);
        }

        for (int ic = 0; ic < 32; ++ic) {
            const float* base = s_in + ic * SIN_IC2 + ty * SIN_ROW2 + cb;
            #pragma unroll
            for (int ky = 0; ky < 3; ++ky) {
                const float* p0 = base + ky * SIN_ROW2;
                const float* p1 = p0 + 16 * SIN_ROW2;
                const float2 a0 = *(const float2*)p0;
                const float2 b0 = *(const float2*)(p0 + 2);
                const float2 a1 = *(const float2*)p1;
                const float2 b1 = *(const float2*)(p1 + 2);
                uint64_t P0[3] = { pack2(a0.x, a0.y), pack2(a0.y, b0.x), pack2(b0.x, b0.y) };
                uint64_t P1[3] = { pack2(a1.x, a1.y), pack2(a1.y, b1.x), pack2(b1.x, b1.y) };
                const ulonglong2* wq =
                    (const ulonglong2*)(s_wd + (ic * 9 + ky * 3) * 8);
                #pragma unroll
                for (int kx = 0; kx < 3; ++kx) {
                    const ulonglong2 w01 = wq[kx * 4 + 0];
                    const ulonglong2 w23 = wq[kx * 4 + 1];
                    const ulonglong2 w45 = wq[kx * 4 + 2];
                    const ulonglong2 w67 = wq[kx * 4 + 3];
                    fma2(acc0[0], P0[kx], w01.x);  fma2(acc1[0], P1[kx], w01.x);
                    fma2(acc0[1], P0[kx], w01.y);  fma2(acc1[1], P1[kx], w01.y);
                    fma2(acc0[2], P0[kx], w23.x);  fma2(acc1[2], P1[kx], w23.x);
                    fma2(acc0[3], P0[kx], w23.y);  fma2(acc1[3], P1[kx], w23.y);
                    fma2(acc0[4], P0[kx], w45.x);  fma2(acc1[4], P1[kx], w45.x);
                    fma2(acc0[5], P0[kx], w45.y);  fma2(acc1[5], P1[kx], w45.y);
                    fma2(acc0[6], P0[kx], w67.x);  fma2(acc1[6], P1[kx], w67.x);
                    fma2(acc0[7], P0[kx], w67.y);  fma2(acc1[7], P1[kx], w67.y);
                }
            }
        }

        // ---- store (or accumulate) 8 oc x 2 rows x 2 px ----
        const int yA = y0 + ty;
        const int yB = yA + 16;
        #pragma unroll
        for (int oc8 = 0; oc8 < 8; ++oc8) {
            const int oc = ocb + oc8;
            if (oc < PCH) {
                float2* dA = (float2*)&g_p[((b * PCH + oc) * HW) + yA * WW + x0g + cb];
                float2* dB = (float2*)&g_p[((b * PCH + oc) * HW) + yB * WW + x0g + cb];
                float2 vA = unpack2(acc0[oc8]);
                float2 vB = unpack2(acc1[oc8]);
                if (accumulate) {
                    const float2 oA = *dA, oB = *dB;
                    vA.x += oA.x; vA.y += oA.y;
                    vB.x += oB.x; vB.y += oB.y;
                }
                *dA = vA;
                *dB = vB;
            }
        }
    }
}

// =========================================================================
// spline: per element compute z + lad; block-reduce lad (deterministic).
// =========================================================================
__device__ __forceinline__ float softplusf(float t) {
    return fmaxf(t, 0.f) + log1pf(expf(-fabsf(t)));
}

__global__ void __launch_bounds__(256) spline_kernel(
    const float* __restrict__ xin,
    float* __restrict__ out)
{
    const int yrow = blockIdx.x;
    const int c    = blockIdx.y;
    const int b    = blockIdx.z;
    const int xcol = threadIdx.x;
    const int pix  = yrow * WW + xcol;

    const int pbase = ((b * PCH + c * 29) * HW) + pix;
    float pv[29];
    #pragma unroll
    for (int j = 0; j < 29; j++) pv[j] = g_p[pbase + j * HW];

    const float xv = xin[((b * C_ + c) * HW) + pix];

    float uw[10];
    #pragma unroll
    for (int j = 0; j < 10; j++) uw[j] = pv[j] * 0.125f;
    float mw = uw[0];
    #pragma unroll
    for (int j = 1; j < 10; j++) mw = fmaxf(mw, uw[j]);
    float ew[10]; float ssum = 0.f;
    #pragma unroll
    for (int j = 0; j < 10; j++) { ew[j] = expf(uw[j] - mw); ssum += ew[j]; }
    float inv = 1.0f / ssum;
    float cw[11]; cw[0] = -1.f;
    {
        float acc = 0.f;
        #pragma unroll
        for (int j = 0; j < 10; j++) {
            float wj = fmaf(0.99f * inv, ew[j], 0.001f);
            acc += wj;
            cw[j + 1] = fmaf(2.f, acc, -1.f);
        }
    }
    cw[10] = 1.f;
    float wd[10];
    #pragma unroll
    for (int j = 0; j < 10; j++) wd[j] = cw[j + 1] - cw[j];

    float uh[10];
    #pragma unroll
    for (int j = 0; j < 10; j++) uh[j] = pv[10 + j] * 0.125f;
    float mh = uh[0];
    #pragma unroll
    for (int j = 1; j < 10; j++) mh = fmaxf(mh, uh[j]);
    float eh[10]; float hsum = 0.f;
    #pragma unroll
    for (int j = 0; j < 10; j++) { eh[j] = expf(uh[j] - mh); hsum += eh[j]; }
    float hinv = 1.0f / hsum;
    float ch[11]; ch[0] = -1.f;
    {
        float acc = 0.f;
        #pragma unroll
        for (int j = 0; j < 10; j++) {
            float hj = fmaf(0.99f * hinv, eh[j], 0.001f);
            acc += hj;
            ch[j + 1] = fmaf(2.f, acc, -1.f);
        }
    }
    ch[10] = 1.f;
    float hd[10];
    #pragma unroll
    for (int j = 0; j < 10; j++) hd[j] = ch[j + 1] - ch[j];

    const float spc = 0.53974215f;
    const float dvE = 0.001f + softplusf(spc);
    float dv[11];
    dv[0] = dvE; dv[10] = dvE;
    #pragma unroll
    for (int j = 1; j < 10; j++) dv[j] = 0.001f + softplusf(pv[19 + j]);

    const float xc = fminf(fmaxf(xv, -1.f), 1.f);
    float icw = cw[0], ibw = wd[0], ich = ch[0], ihh = hd[0], d0 = dv[0], d1 = dv[1];
    #pragma unroll
    for (int k = 1; k < 10; k++) {
        if (xc >= cw[k]) {
            icw = cw[k]; ibw = wd[k]; ich = ch[k]; ihh = hd[k];
            d0 = dv[k]; d1 = dv[k + 1];
        }
    }

    const float idl   = ihh / ibw;
    const float theta = (xc - icw) / ibw;
    const float th2   = theta * theta;
    const float tt    = theta * (1.f - theta);
    const float numer = ihh * (idl * th2 + d0 * tt);
    const float denom = idl + (d0 + d1 - 2.f * idl) * tt;
    const float zin   = ich + numer / denom;
    const float omt   = 1.f - theta;
    const float dnum  = idl * idl * (d1 * th2 + 2.f * idl * tt + d0 * omt * omt);
    const float ladv  = logf(dnum) - 2.f * logf(denom);

    const bool inside = (xv >= -1.f) && (xv <= 1.f);
    const float z = inside ? zin : xv;
    float l       = inside ? ladv : 0.f;

    out[((b * C_ + c) * HW) + pix] = z;

    #pragma unroll
    for (int off = 16; off; off >>= 1)
        l += __shfl_down_sync(0xffffffffu, l, off);
    __shared__ float wr[8];
    const int wid = threadIdx.x >> 5, lane = threadIdx.x & 31;
    if (lane == 0) wr[wid] = l;
    __syncthreads();
    if (threadIdx.x == 0) {
        float s = 0.f;
        #pragma unroll
        for (int i = 0; i < 8; i++) s += wr[i];
        g_partial[(b * C_ + c) * HH + yrow] = s;
    }
}

// =========================================================================
__global__ void __launch_bounds__(256) reduce_kernel(float* __restrict__ out)
{
    const int b = blockIdx.x;
    const int tid = threadIdx.x;
    __shared__ double sd[256];
    double s = 0.0;
    #pragma unroll
    for (int i = 0; i < 4; i++)
        s += (double)g_partial[b * 1024 + tid + i * 256];
    sd[tid] = s;
    __syncthreads();
    for (int off = 128; off; off >>= 1) {
        if (tid < off) sd[tid] += sd[tid + off];
        __syncthreads();
    }
    if (tid == 0) out[B_ * C_ * HW + b] = (float)sd[0];
}

// =========================================================================
extern "C" void kernel_launch(void* const* d_in, const int* in_sizes, int n_in,
                              void* d_out, int out_size)
{
    const float* x     = (const float*)d_in[0];
    const float* clean = (const float*)d_in[1];
    const float* W1    = (const float*)d_in[2];
    const float* b1    = (const float*)d_in[3];
    const float* W2    = (const float*)d_in[4];
    const float* b2    = (const float*)d_in[5];
    float* out = (float*)d_out;

    cudaFuncSetAttribute(conv2_kernel,
                         cudaFuncAttributeMaxDynamicSharedMemorySize, SMEM2);

    conv1_kernel<<<dim3(256, 16, 16), 256>>>(clean, W1, b1);
    conv2_kernel<<<dim3(8, 8, 16), 256, SMEM2>>>(W2, b2, 0, 0);
    conv2_kernel<<<dim3(8, 8, 16), 256, SMEM2>>>(W2, b2, 32, 1);
    spline_kernel<<<dim3(256, 4, 16), 256>>>(x, out);
    reduce_kernel<<<16, 256>>>(out);
}

// round 6
// speedup vs baseline: 4.1006x; 2.5579x over previous
#include <cuda_runtime.h>
#include <cuda_bf16.h>
#include <cstdint>

#define B_   16
#define C_   4
#define HH   256
#define WW   256
#define HID  64
#define PCH  116          // C_*(3*10-1)
#define HW   (HH*WW)      // 65536

// ---------------- device scratch (no allocations allowed) ----------------
__device__ float g_hid[B_ * HID * HW];        // 268 MB
__device__ float g_p  [B_ * PCH * HW];        // 486 MB
__device__ float g_partial[B_ * C_ * HH];     // partial lad sums
// W2 pre-packed into exact mma.m16n8k16 B-fragment layout, bf16 hi/lo:
// index = ((j*4 + ks)*16 + nt)*64 + lane*2 + r   (uint32 = bf16x2)
__device__ __align__(16) uint32_t g_WfHi[9 * 4 * 16 * 64];
__device__ __align__(16) uint32_t g_WfLo[9 * 4 * 16 * 64];

// ======================= helpers =====================
__device__ __forceinline__ uint32_t smem_to_u32(const void* p) {
    uint32_t a;
    asm("{ .reg .u64 t; cvta.to.shared.u64 t, %1; cvt.u32.u64 %0, t; }"
        : "=r"(a) : "l"(p));
    return a;
}
#define SMEM_SWIZZLE_128B(o) ((o) ^ (((o) >> 3) & 0x70))

#define STS128(r0, r1, r2, r3, a) \
    asm volatile("st.shared.v4.b32 [%0], {%1, %2, %3, %4};" \
        :: "r"(a), "r"(r0), "r"(r1), "r"(r2), "r"(r3) : "memory")

__device__ __forceinline__ void ldsm_x4(uint32_t* r, uint32_t addr) {
    asm volatile("ldmatrix.sync.aligned.m8n8.x4.shared.b16 {%0,%1,%2,%3}, [%4];"
        : "=r"(r[0]), "=r"(r[1]), "=r"(r[2]), "=r"(r[3]) : "r"(addr));
}
__device__ __forceinline__ void mma_bf16(float* d, const uint32_t* a,
                                         const uint32_t* b) {
    asm volatile(
        "mma.sync.aligned.m16n8k16.row.col.f32.bf16.bf16.f32 "
        "{%0,%1,%2,%3}, {%4,%5,%6,%7}, {%8,%9}, {%0,%1,%2,%3};"
        : "+f"(d[0]), "+f"(d[1]), "+f"(d[2]), "+f"(d[3])
        : "r"(a[0]), "r"(a[1]), "r"(a[2]), "r"(a[3]),
          "r"(b[0]), "r"(b[1]));
}

// =========================================================================
// conv1: clean[16,4,256,256] -> relu(conv3x3) -> g_hid
// =========================================================================
__global__ void __launch_bounds__(256) conv1_kernel(
    const float* __restrict__ clean,
    const float* __restrict__ W1,
    const float* __restrict__ b1)
{
    __shared__ float2 s_wp[36 * 2];
    __shared__ float  s_b[4];

    const int y = blockIdx.x;
    const int g = blockIdx.y;
    const int b = blockIdx.z;
    const int tid = threadIdx.x;

    if (tid < 72) {
        int k = tid >> 1, half = tid & 1;
        int oc0 = g * 4 + 2 * half;
        s_wp[2 * k + half] = make_float2(W1[oc0 * 36 + k], W1[(oc0 + 1) * 36 + k]);
    }
    if (tid < 4) s_b[tid] = b1[g * 4 + tid];
    __syncthreads();

    float2 aA = make_float2(s_b[0], s_b[1]);
    float2 aB = make_float2(s_b[2], s_b[3]);

    #pragma unroll
    for (int ic = 0; ic < 4; ic++) {
        #pragma unroll
        for (int ky = 0; ky < 3; ky++) {
            const int yy = y + ky - 1;
            const bool yok = ((unsigned)yy < 256u);
            #pragma unroll
            for (int kx = 0; kx < 3; kx++) {
                const int xx = tid + kx - 1;
                float v = 0.f;
                if (yok && (unsigned)xx < 256u)
                    v = clean[((b * 4 + ic) * HW) + yy * WW + xx];
                const int k = ic * 9 + ky * 3 + kx;
                float2 wA = s_wp[2 * k], wB = s_wp[2 * k + 1];
                aA.x = fmaf(v, wA.x, aA.x); aA.y = fmaf(v, wA.y, aA.y);
                aB.x = fmaf(v, wB.x, aB.x); aB.y = fmaf(v, wB.y, aB.y);
            }
        }
    }
    const int o = ((b * HID + g * 4) * HW) + y * WW + tid;
    g_hid[o         ] = fmaxf(aA.x, 0.f);
    g_hid[o +     HW] = fmaxf(aA.y, 0.f);
    g_hid[o + 2 * HW] = fmaxf(aB.x, 0.f);
    g_hid[o + 3 * HW] = fmaxf(aB.y, 0.f);
}

// =========================================================================
// prep_w: pack W2 into mma B-fragment layout (bf16 hi/lo split).
// Fragment element mapping (m16n8k16 .col B): n = nt*8 + lane/4,
// k(=ic) = ks*16 + r*8 + (lane%4)*2 + {0,1}; reg = bf16x2 (low = even k).
// =========================================================================
__global__ void __launch_bounds__(256) prep_w_kernel(const float* __restrict__ W2)
{
    const int i = blockIdx.x * 256 + threadIdx.x;   // over 36864
    if (i >= 9 * 4 * 16 * 64) return;
    const int r    = i & 1;
    const int lane = (i >> 1) & 31;
    const int nt   = (i >> 6) & 15;
    const int ks   = (i >> 10) & 3;
    const int j    = i >> 12;                       // 0..8 = ky*3+kx
    const int n    = nt * 8 + (lane >> 2);
    const int ic0  = ks * 16 + r * 8 + (lane & 3) * 2;

    float w0 = 0.f, w1 = 0.f;
    if (n < PCH) {
        w0 = W2[n * 576 + ic0 * 9 + j];
        w1 = W2[n * 576 + (ic0 + 1) * 9 + j];
    }
    __nv_bfloat16 h0 = __float2bfloat16(w0);
    __nv_bfloat16 h1 = __float2bfloat16(w1);
    float f0 = __bfloat162float(h0), f1 = __bfloat162float(h1);
    __nv_bfloat16 l0 = __float2bfloat16(w0 - f0);
    __nv_bfloat16 l1 = __float2bfloat16(w1 - f1);
    uint16_t uh0 = *(uint16_t*)&h0, uh1 = *(uint16_t*)&h1;
    uint16_t ul0 = *(uint16_t*)&l0, ul1 = *(uint16_t*)&l1;
    g_WfHi[i] = (uint32_t)uh0 | ((uint32_t)uh1 << 16);
    g_WfLo[i] = (uint32_t)ul0 | ((uint32_t)ul1 << 16);
}

// =========================================================================
// conv2 via mma.sync (HMMA bf16, 3-pass hi/lo split):
// CTA = 128 x-pixels of one row y  x  128 (padded) oc.  K = 9 chunks of 64.
// A chunk in SMEM (SW128) via ldmatrix; W fragments direct from global.
// Warp tiling: m-group = wid&1 (64 rows), n-group = wid>>1 (32 cols).
// =========================================================================
#define SMEM_TC  67584    // max(A bufs 32KB, epilogue 128*132*4 = 67584)

__global__ void __launch_bounds__(256) conv2_tc_kernel(const float* __restrict__ b2)
{
    extern __shared__ char smem[];
    __shared__ float s_b2[128];
    const uint32_t sb = smem_to_u32(smem);
    const int tid = threadIdx.x, wid = tid >> 5, lane = tid & 31;
    const int x0 = blockIdx.x * 128;
    const int y  = blockIdx.y;
    const int b  = blockIdx.z;
    const int mg = wid & 1;          // m-group (64 rows)
    const int ng = wid >> 1;         // n-group (32 cols)

    if (tid < 128) s_b2[tid] = (tid < PCH) ? b2[tid] : 0.f;

    const uint32_t aHi = sb;
    const uint32_t aLo = sb + 16384;

    float d[4][4][4];
    #pragma unroll
    for (int mt = 0; mt < 4; ++mt)
        #pragma unroll
        for (int nt = 0; nt < 4; ++nt)
            #pragma unroll
            for (int r = 0; r < 4; ++r) d[mt][nt][r] = 0.f;

    for (int j = 0; j < 9; ++j) {
        const int ky = j / 3, kx = j - 3 * ky;
        __syncthreads();   // chunk j-1 fully consumed before overwrite

        // ---- build A chunk [m=0..127][ic=0..63] bf16 hi/lo, SW128 ----
        {
            const int yy  = y + ky - 1;
            const bool yok = ((unsigned)yy < 256u);
            const int icb = 8 * wid;
            #pragma unroll
            for (int jj = 0; jj < 4; ++jj) {
                const int m  = lane + 32 * jj;
                const int xx = x0 + m + kx - 1;
                const bool ok = yok && ((unsigned)xx < 256u);
                float v[8];
                const int base = ((b * HID + icb) * HW) + yy * WW + xx;
                #pragma unroll
                for (int icl = 0; icl < 8; ++icl)
                    v[icl] = ok ? g_hid[base + icl * HW] : 0.f;
                uint32_t h[4], l[4];
                #pragma unroll
                for (int p = 0; p < 4; ++p) {
                    asm("cvt.rn.bf16x2.f32 %0, %1, %2;"
                        : "=r"(h[p]) : "f"(v[2*p+1]), "f"(v[2*p]));
                    const float f0 = __uint_as_float(h[p] << 16);
                    const float f1 = __uint_as_float(h[p] & 0xffff0000u);
                    asm("cvt.rn.bf16x2.f32 %0, %1, %2;"
                        : "=r"(l[p]) : "f"(v[2*p+1] - f1), "f"(v[2*p] - f0));
                }
                const uint32_t off =
                    SMEM_SWIZZLE_128B((uint32_t)(m * 128 + wid * 16));
                STS128(h[0], h[1], h[2], h[3], aHi + off);
                STS128(l[0], l[1], l[2], l[3], aLo + off);
            }
        }
        __syncthreads();

        // ---- 4 K-steps of 16 ----
        #pragma unroll
        for (int ks = 0; ks < 4; ++ks) {
            uint32_t ah[4][4], al[4][4];
            const uint32_t cbyte = ks * 32 + (lane >> 4) * 16;
            #pragma unroll
            for (int mt = 0; mt < 4; ++mt) {
                const uint32_t row = (uint32_t)((mg * 64 + mt * 16 + (lane & 15)) * 128);
                const uint32_t off = SMEM_SWIZZLE_128B(row + cbyte);
                ldsm_x4(ah[mt], aHi + off);
                ldsm_x4(al[mt], aLo + off);
            }
            uint32_t bh[4][2], bl[4][2];
            #pragma unroll
            for (int nt4 = 0; nt4 < 4; ++nt4) {
                const int nt = ng * 4 + nt4;
                const int idx = ((j * 4 + ks) * 16 + nt) * 32 + lane;
                const uint2 vh = ((const uint2*)g_WfHi)[idx];
                const uint2 vl = ((const uint2*)g_WfLo)[idx];
                bh[nt4][0] = vh.x; bh[nt4][1] = vh.y;
                bl[nt4][0] = vl.x; bl[nt4][1] = vl.y;
            }
            #pragma unroll
            for (int mt = 0; mt < 4; ++mt)
                #pragma unroll
                for (int nt4 = 0; nt4 < 4; ++nt4) {
                    mma_bf16(d[mt][nt4], ah[mt], bh[nt4]);
                    mma_bf16(d[mt][nt4], al[mt], bh[nt4]);
                    mma_bf16(d[mt][nt4], ah[mt], bl[nt4]);
                }
        }
    }

    // ---- epilogue: stage to padded smem, then coalesced stores ----
    __syncthreads();
    float* s_out = (float*)smem;     // [n=128][m padded to 132]
    #pragma unroll
    for (int mt = 0; mt < 4; ++mt)
        #pragma unroll
        for (int nt4 = 0; nt4 < 4; ++nt4)
            #pragma unroll
            for (int r = 0; r < 4; ++r) {
                const int m = mg * 64 + mt * 16 + (lane >> 2) + ((r >> 1) * 8);
                const int n = ng * 32 + nt4 * 8 + (lane & 3) * 2 + (r & 1);
                s_out[n * 132 + m] = d[mt][nt4][r];
            }
    __syncthreads();
    #pragma unroll
    for (int i = 0; i < 16; ++i) {
        const int fi = tid + i * 256;    // float4 index over [128][32]
        const int n  = fi >> 5, c4 = fi & 31;
        if (n < PCH) {
            float4 v = *(float4*)&s_out[n * 132 + c4 * 4];
            const float bb = s_b2[n];
            v.x += bb; v.y += bb; v.z += bb; v.w += bb;
            *(float4*)&g_p[((b * PCH + n) * HW) + y * WW + x0 + c4 * 4] = v;
        }
    }
}

// =========================================================================
// spline: per element compute z + lad; block-reduce lad (deterministic).
// =========================================================================
__device__ __forceinline__ float softplusf(float t) {
    return fmaxf(t, 0.f) + log1pf(expf(-fabsf(t)));
}

__global__ void __launch_bounds__(256) spline_kernel(
    const float* __restrict__ xin,
    float* __restrict__ out)
{
    const int yrow = blockIdx.x;
    const int c    = blockIdx.y;
    const int b    = blockIdx.z;
    const int xcol = threadIdx.x;
    const int pix  = yrow * WW + xcol;

    const int pbase = ((b * PCH + c * 29) * HW) + pix;
    float pv[29];
    #pragma unroll
    for (int j = 0; j < 29; j++) pv[j] = g_p[pbase + j * HW];

    const float xv = xin[((b * C_ + c) * HW) + pix];

    float uw[10];
    #pragma unroll
    for (int j = 0; j < 10; j++) uw[j] = pv[j] * 0.125f;
    float mw = uw[0];
    #pragma unroll
    for (int j = 1; j < 10; j++) mw = fmaxf(mw, uw[j]);
    float ew[10]; float ssum = 0.f;
    #pragma unroll
    for (int j = 0; j < 10; j++) { ew[j] = expf(uw[j] - mw); ssum += ew[j]; }
    float inv = 1.0f / ssum;
    float cw[11]; cw[0] = -1.f;
    {
        float acc = 0.f;
        #pragma unroll
        for (int j = 0; j < 10; j++) {
            float wj = fmaf(0.99f * inv, ew[j], 0.001f);
            acc += wj;
            cw[j + 1] = fmaf(2.f, acc, -1.f);
        }
    }
    cw[10] = 1.f;
    float wd[10];
    #pragma unroll
    for (int j = 0; j < 10; j++) wd[j] = cw[j + 1] - cw[j];

    float uh[10];
    #pragma unroll
    for (int j = 0; j < 10; j++) uh[j] = pv[10 + j] * 0.125f;
    float mh = uh[0];
    #pragma unroll
    for (int j = 1; j < 10; j++) mh = fmaxf(mh, uh[j]);
    float eh[10]; float hsum = 0.f;
    #pragma unroll
    for (int j = 0; j < 10; j++) { eh[j] = expf(uh[j] - mh); hsum += eh[j]; }
    float hinv = 1.0f / hsum;
    float ch[11]; ch[0] = -1.f;
    {
        float acc = 0.f;
        #pragma unroll
        for (int j = 0; j < 10; j++) {
            float hj = fmaf(0.99f * hinv, eh[j], 0.001f);
            acc += hj;
            ch[j + 1] = fmaf(2.f, acc, -1.f);
        }
    }
    ch[10] = 1.f;
    float hd[10];
    #pragma unroll
    for (int j = 0; j < 10; j++) hd[j] = ch[j + 1] - ch[j];

    const float spc = 0.53974215f;
    const float dvE = 0.001f + softplusf(spc);
    float dv[11];
    dv[0] = dvE; dv[10] = dvE;
    #pragma unroll
    for (int j = 1; j < 10; j++) dv[j] = 0.001f + softplusf(pv[19 + j]);

    const float xc = fminf(fmaxf(xv, -1.f), 1.f);
    float icw = cw[0], ibw = wd[0], ich = ch[0], ihh = hd[0], d0 = dv[0], d1 = dv[1];
    #pragma unroll
    for (int k = 1; k < 10; k++) {
        if (xc >= cw[k]) {
            icw = cw[k]; ibw = wd[k]; ich = ch[k]; ihh = hd[k];
            d0 = dv[k]; d1 = dv[k + 1];
        }
    }

    const float idl   = ihh / ibw;
    const float theta = (xc - icw) / ibw;
    const float th2   = theta * theta;
    const float tt    = theta * (1.f - theta);
    const float numer = ihh * (idl * th2 + d0 * tt);
    const float denom = idl + (d0 + d1 - 2.f * idl) * tt;
    const float zin   = ich + numer / denom;
    const float omt   = 1.f - theta;
    const float dnum  = idl * idl * (d1 * th2 + 2.f * idl * tt + d0 * omt * omt);
    const float ladv  = logf(dnum) - 2.f * logf(denom);

    const bool inside = (xv >= -1.f) && (xv <= 1.f);
    const float z = inside ? zin : xv;
    float l       = inside ? ladv : 0.f;

    out[((b * C_ + c) * HW) + pix] = z;

    #pragma unroll
    for (int off = 16; off; off >>= 1)
        l += __shfl_down_sync(0xffffffffu, l, off);
    __shared__ float wr[8];
    const int wid = threadIdx.x >> 5, lane = threadIdx.x & 31;
    if (lane == 0) wr[wid] = l;
    __syncthreads();
    if (threadIdx.x == 0) {
        float s = 0.f;
        #pragma unroll
        for (int i = 0; i < 8; i++) s += wr[i];
        g_partial[(b * C_ + c) * HH + yrow] = s;
    }
}

// =========================================================================
__global__ void __launch_bounds__(256) reduce_kernel(float* __restrict__ out)
{
    const int b = blockIdx.x;
    const int tid = threadIdx.x;
    __shared__ double sd[256];
    double s = 0.0;
    #pragma unroll
    for (int i = 0; i < 4; i++)
        s += (double)g_partial[b * 1024 + tid + i * 256];
    sd[tid] = s;
    __syncthreads();
    for (int off = 128; off; off >>= 1) {
        if (tid < off) sd[tid] += sd[tid + off];
        __syncthreads();
    }
    if (tid == 0) out[B_ * C_ * HW + b] = (float)sd[0];
}

// =========================================================================
extern "C" void kernel_launch(void* const* d_in, const int* in_sizes, int n_in,
                              void* d_out, int out_size)
{
    const float* x     = (const float*)d_in[0];
    const float* clean = (const float*)d_in[1];
    const float* W1    = (const float*)d_in[2];
    const float* b1    = (const float*)d_in[3];
    const float* W2    = (const float*)d_in[4];
    const float* b2    = (const float*)d_in[5];
    float* out = (float*)d_out;

    cudaFuncSetAttribute(conv2_tc_kernel,
                         cudaFuncAttributeMaxDynamicSharedMemorySize, SMEM_TC);

    conv1_kernel<<<dim3(256, 16, 16), 256>>>(clean, W1, b1);
    prep_w_kernel<<<144, 256>>>(W2);
    conv2_tc_kernel<<<dim3(2, 256, 16), 256, SMEM_TC>>>(b2);
    spline_kernel<<<dim3(256, 4, 16), 256>>>(x, out);
    reduce_kernel<<<16, 256>>>(out);
}

// round 7
// speedup vs baseline: 4.6896x; 1.1437x over previous
#include <cuda_runtime.h>
#include <cuda_bf16.h>
#include <cstdint>

#define B_   16
#define C_   4
#define HH   256
#define WW   256
#define HID  64
#define PCH  116          // C_*(3*10-1)
#define HW   (HH*WW)      // 65536

// ---------------- device scratch (no allocations allowed) ----------------
__device__ float g_hid[B_ * HID * HW];        // 268 MB
__device__ float g_partial[B_ * HH * 2];      // per-(b,y,xtile) lad partials
// W2 pre-packed into exact mma.m16n8k16 B-fragment layout, bf16 hi/lo:
__device__ __align__(16) uint32_t g_WfHi[9 * 4 * 16 * 64];
__device__ __align__(16) uint32_t g_WfLo[9 * 4 * 16 * 64];

// ======================= helpers =====================
__device__ __forceinline__ uint32_t smem_to_u32(const void* p) {
    uint32_t a;
    asm("{ .reg .u64 t; cvta.to.shared.u64 t, %1; cvt.u32.u64 %0, t; }"
        : "=r"(a) : "l"(p));
    return a;
}
#define SMEM_SWIZZLE_128B(o) ((o) ^ (((o) >> 3) & 0x70))

#define STS128(r0, r1, r2, r3, a) \
    asm volatile("st.shared.v4.b32 [%0], {%1, %2, %3, %4};" \
        :: "r"(a), "r"(r0), "r"(r1), "r"(r2), "r"(r3) : "memory")

__device__ __forceinline__ void ldsm_x4(uint32_t* r, uint32_t addr) {
    asm volatile("ldmatrix.sync.aligned.m8n8.x4.shared.b16 {%0,%1,%2,%3}, [%4];"
        : "=r"(r[0]), "=r"(r[1]), "=r"(r[2]), "=r"(r[3]) : "r"(addr));
}
__device__ __forceinline__ void mma_bf16(float* d, const uint32_t* a,
                                         const uint32_t* b) {
    asm volatile(
        "mma.sync.aligned.m16n8k16.row.col.f32.bf16.bf16.f32 "
        "{%0,%1,%2,%3}, {%4,%5,%6,%7}, {%8,%9}, {%0,%1,%2,%3};"
        : "+f"(d[0]), "+f"(d[1]), "+f"(d[2]), "+f"(d[3])
        : "r"(a[0]), "r"(a[1]), "r"(a[2]), "r"(a[3]),
          "r"(b[0]), "r"(b[1]));
}

// =========================================================================
// conv1: clean[16,4,256,256] -> relu(conv3x3) -> g_hid
// =========================================================================
__global__ void __launch_bounds__(256) conv1_kernel(
    const float* __restrict__ clean,
    const float* __restrict__ W1,
    const float* __restrict__ b1)
{
    __shared__ float2 s_wp[36 * 2];
    __shared__ float  s_b[4];

    const int y = blockIdx.x;
    const int g = blockIdx.y;
    const int b = blockIdx.z;
    const int tid = threadIdx.x;

    if (tid < 72) {
        int k = tid >> 1, half = tid & 1;
        int oc0 = g * 4 + 2 * half;
        s_wp[2 * k + half] = make_float2(W1[oc0 * 36 + k], W1[(oc0 + 1) * 36 + k]);
    }
    if (tid < 4) s_b[tid] = b1[g * 4 + tid];
    __syncthreads();

    float2 aA = make_float2(s_b[0], s_b[1]);
    float2 aB = make_float2(s_b[2], s_b[3]);

    #pragma unroll
    for (int ic = 0; ic < 4; ic++) {
        #pragma unroll
        for (int ky = 0; ky < 3; ky++) {
            const int yy = y + ky - 1;
            const bool yok = ((unsigned)yy < 256u);
            #pragma unroll
            for (int kx = 0; kx < 3; kx++) {
                const int xx = tid + kx - 1;
                float v = 0.f;
                if (yok && (unsigned)xx < 256u)
                    v = clean[((b * 4 + ic) * HW) + yy * WW + xx];
                const int k = ic * 9 + ky * 3 + kx;
                float2 wA = s_wp[2 * k], wB = s_wp[2 * k + 1];
                aA.x = fmaf(v, wA.x, aA.x); aA.y = fmaf(v, wA.y, aA.y);
                aB.x = fmaf(v, wB.x, aB.x); aB.y = fmaf(v, wB.y, aB.y);
            }
        }
    }
    const int o = ((b * HID + g * 4) * HW) + y * WW + tid;
    g_hid[o         ] = fmaxf(aA.x, 0.f);
    g_hid[o +     HW] = fmaxf(aA.y, 0.f);
    g_hid[o + 2 * HW] = fmaxf(aB.x, 0.f);
    g_hid[o + 3 * HW] = fmaxf(aB.y, 0.f);
}

// =========================================================================
// prep_w: pack W2 into mma B-fragment layout (bf16 hi/lo split).
// =========================================================================
__global__ void __launch_bounds__(256) prep_w_kernel(const float* __restrict__ W2)
{
    const int i = blockIdx.x * 256 + threadIdx.x;   // over 36864
    if (i >= 9 * 4 * 16 * 64) return;
    const int r    = i & 1;
    const int lane = (i >> 1) & 31;
    const int nt   = (i >> 6) & 15;
    const int ks   = (i >> 10) & 3;
    const int j    = i >> 12;                       // 0..8 = ky*3+kx
    const int n    = nt * 8 + (lane >> 2);
    const int ic0  = ks * 16 + r * 8 + (lane & 3) * 2;

    float w0 = 0.f, w1 = 0.f;
    if (n < PCH) {
        w0 = W2[n * 576 + ic0 * 9 + j];
        w1 = W2[n * 576 + (ic0 + 1) * 9 + j];
    }
    __nv_bfloat16 h0 = __float2bfloat16(w0);
    __nv_bfloat16 h1 = __float2bfloat16(w1);
    float f0 = __bfloat162float(h0), f1 = __bfloat162float(h1);
    __nv_bfloat16 l0 = __float2bfloat16(w0 - f0);
    __nv_bfloat16 l1 = __float2bfloat16(w1 - f1);
    uint16_t uh0 = *(uint16_t*)&h0, uh1 = *(uint16_t*)&h1;
    uint16_t ul0 = *(uint16_t*)&l0, ul1 = *(uint16_t*)&l1;
    g_WfHi[i] = (uint32_t)uh0 | ((uint32_t)uh1 << 16);
    g_WfLo[i] = (uint32_t)ul0 | ((uint32_t)ul1 << 16);
}

// =========================================================================
// fused conv2 (HMMA bf16 3-pass) + bias + spline + lad partial reduction.
// CTA = 128 x-pixels of one row y x 128 (padded) oc. K = 3 ky-builds x 3 kx.
// A built once per ky into a 130-row buffer; kx = ldmatrix row offset.
// =========================================================================
#define ABUF_B   33280        // 130*128*2 (hi+lo planes)
#define SMEM_TC  67840        // max(2 A bufs 66560, epilogue 128*132*4=67584)

__device__ __forceinline__ float softplus_fast(float t) {
    return fmaxf(t, 0.f) + __logf(1.f + __expf(-fabsf(t)));
}

__global__ void __launch_bounds__(256) conv2_fused_kernel(
    const float* __restrict__ b2,
    const float* __restrict__ xin,
    float* __restrict__ out)
{
    extern __shared__ char smem[];
    __shared__ float s_b2[128];
    __shared__ float s_wr[8];
    const uint32_t sb = smem_to_u32(smem);
    const int tid = threadIdx.x, wid = tid >> 5, lane = tid & 31;
    const int x0 = blockIdx.x * 128;
    const int y  = blockIdx.y;
    const int b  = blockIdx.z;
    const int mg = wid & 1;          // m-group (64 rows)
    const int ng = wid >> 1;         // n-group (32 cols)

    if (tid < 128) s_b2[tid] = (tid < PCH) ? b2[tid] : 0.f;

    float d[4][4][4];
    #pragma unroll
    for (int mt = 0; mt < 4; ++mt)
        #pragma unroll
        for (int nt = 0; nt < 4; ++nt)
            #pragma unroll
            for (int r = 0; r < 4; ++r) d[mt][nt][r] = 0.f;

    for (int ky = 0; ky < 3; ++ky) {
        const uint32_t aHi = sb + (ky & 1) * ABUF_B;
        const uint32_t aLo = aHi + 16640;

        // ---- build A rows mm=0..129 (x0+mm-1), 64 ic, bf16 hi/lo, SW128 ----
        {
            const int yy  = y + ky - 1;
            const bool yok = ((unsigned)yy < 256u);
            for (int i = tid; i < 130 * 4; i += 256) {
                const int mm = i >> 2, q = i & 3;
                const int xx = x0 + mm - 1;
                const bool ok = yok && ((unsigned)xx < 256u);
                float v[16];
                const int base = ((b * HID + q * 16) * HW) + yy * WW + xx;
                #pragma unroll
                for (int icl = 0; icl < 16; ++icl)
                    v[icl] = ok ? g_hid[base + icl * HW] : 0.f;
                uint32_t h[8], l[8];
                #pragma unroll
                for (int p = 0; p < 8; ++p) {
                    asm("cvt.rn.bf16x2.f32 %0, %1, %2;"
                        : "=r"(h[p]) : "f"(v[2*p+1]), "f"(v[2*p]));
                    const float f0 = __uint_as_float(h[p] << 16);
                    const float f1 = __uint_as_float(h[p] & 0xffff0000u);
                    asm("cvt.rn.bf16x2.f32 %0, %1, %2;"
                        : "=r"(l[p]) : "f"(v[2*p+1] - f1), "f"(v[2*p] - f0));
                }
                const uint32_t o0 = SMEM_SWIZZLE_128B((uint32_t)(mm * 128 + q * 32));
                const uint32_t o1 = SMEM_SWIZZLE_128B((uint32_t)(mm * 128 + q * 32 + 16));
                STS128(h[0], h[1], h[2], h[3], aHi + o0);
                STS128(h[4], h[5], h[6], h[7], aHi + o1);
                STS128(l[0], l[1], l[2], l[3], aLo + o0);
                STS128(l[4], l[5], l[6], l[7], aLo + o1);
            }
        }
        __syncthreads();

        // ---- consume: 3 kx chunks x 4 K-steps ----
        for (int kx = 0; kx < 3; ++kx) {
            const int j = ky * 3 + kx;
            #pragma unroll
            for (int ks = 0; ks < 4; ++ks) {
                uint32_t ah[4][4], al[4][4];
                const uint32_t cbyte = ks * 32 + (lane >> 4) * 16;
                #pragma unroll
                for (int mt = 0; mt < 4; ++mt) {
                    const uint32_t row =
                        (uint32_t)(mg * 64 + mt * 16 + (lane & 15) + kx);
                    const uint32_t off = SMEM_SWIZZLE_128B(row * 128 + cbyte);
                    ldsm_x4(ah[mt], aHi + off);
                    ldsm_x4(al[mt], aLo + off);
                }
                uint32_t bh[4][2], bl[4][2];
                #pragma unroll
                for (int nt4 = 0; nt4 < 4; ++nt4) {
                    const int nt = ng * 4 + nt4;
                    const int idx = ((j * 4 + ks) * 16 + nt) * 32 + lane;
                    const uint2 vh = ((const uint2*)g_WfHi)[idx];
                    const uint2 vl = ((const uint2*)g_WfLo)[idx];
                    bh[nt4][0] = vh.x; bh[nt4][1] = vh.y;
                    bl[nt4][0] = vl.x; bl[nt4][1] = vl.y;
                }
                #pragma unroll
                for (int mt = 0; mt < 4; ++mt)
                    #pragma unroll
                    for (int nt4 = 0; nt4 < 4; ++nt4) {
                        mma_bf16(d[mt][nt4], ah[mt], bh[nt4]);
                        mma_bf16(d[mt][nt4], al[mt], bh[nt4]);
                        mma_bf16(d[mt][nt4], ah[mt], bl[nt4]);
                    }
            }
        }
        __syncthreads();
    }

    // ---- stage result: s_out[n=0..127][m padded 132] ----
    float* s_out = (float*)smem;
    #pragma unroll
    for (int mt = 0; mt < 4; ++mt)
        #pragma unroll
        for (int nt4 = 0; nt4 < 4; ++nt4)
            #pragma unroll
            for (int r = 0; r < 4; ++r) {
                const int m = mg * 64 + mt * 16 + (lane >> 2) + ((r >> 1) * 8);
                const int n = ng * 32 + nt4 * 8 + (lane & 3) * 2 + (r & 1);
                s_out[n * 132 + m] = d[mt][nt4][r];
            }
    __syncthreads();

    // ---- fused spline: thread handles pixels m=tid&127 for c0 and c0+2 ----
    float ladsum = 0.f;
    {
        const int m  = tid & 127;
        const int c0 = tid >> 7;
        #pragma unroll
        for (int e = 0; e < 2; ++e) {
            const int c = c0 + 2 * e;
            float pv[29];
            #pragma unroll
            for (int j = 0; j < 29; j++)
                pv[j] = s_out[(c * 29 + j) * 132 + m] + s_b2[c * 29 + j];

            const float xv = xin[((b * C_ + c) * HW) + y * WW + x0 + m];

            float uw[10];
            #pragma unroll
            for (int j = 0; j < 10; j++) uw[j] = pv[j] * 0.125f;
            float mw = uw[0];
            #pragma unroll
            for (int j = 1; j < 10; j++) mw = fmaxf(mw, uw[j]);
            float ew[10]; float ssum = 0.f;
            #pragma unroll
            for (int j = 0; j < 10; j++) { ew[j] = __expf(uw[j] - mw); ssum += ew[j]; }
            float inv = 1.0f / ssum;
            float cw[11]; cw[0] = -1.f;
            {
                float acc = 0.f;
                #pragma unroll
                for (int j = 0; j < 10; j++) {
                    float wj = fmaf(0.99f * inv, ew[j], 0.001f);
                    acc += wj;
                    cw[j + 1] = fmaf(2.f, acc, -1.f);
                }
            }
            cw[10] = 1.f;
            float wd[10];
            #pragma unroll
            for (int j = 0; j < 10; j++) wd[j] = cw[j + 1] - cw[j];

            float uh[10];
            #pragma unroll
            for (int j = 0; j < 10; j++) uh[j] = pv[10 + j] * 0.125f;
            float mh = uh[0];
            #pragma unroll
            for (int j = 1; j < 10; j++) mh = fmaxf(mh, uh[j]);
            float eh[10]; float hsum = 0.f;
            #pragma unroll
            for (int j = 0; j < 10; j++) { eh[j] = __expf(uh[j] - mh); hsum += eh[j]; }
            float hinv = 1.0f / hsum;
            float ch[11]; ch[0] = -1.f;
            {
                float acc = 0.f;
                #pragma unroll
                for (int j = 0; j < 10; j++) {
                    float hj = fmaf(0.99f * hinv, eh[j], 0.001f);
                    acc += hj;
                    ch[j + 1] = fmaf(2.f, acc, -1.f);
                }
            }
            ch[10] = 1.f;
            float hd[10];
            #pragma unroll
            for (int j = 0; j < 10; j++) hd[j] = ch[j + 1] - ch[j];

            const float spc = 0.53974215f;          // log(exp(0.999)-1)
            const float dvE = 0.001f + softplus_fast(spc);
            float dv[11];
            dv[0] = dvE; dv[10] = dvE;
            #pragma unroll
            for (int j = 1; j < 10; j++) dv[j] = 0.001f + softplus_fast(pv[19 + j]);

            const float xc = fminf(fmaxf(xv, -1.f), 1.f);
            float icw = cw[0], ibw = wd[0], ich = ch[0], ihh = hd[0];
            float d0 = dv[0], d1 = dv[1];
            #pragma unroll
            for (int k = 1; k < 10; k++) {
                if (xc >= cw[k]) {
                    icw = cw[k]; ibw = wd[k]; ich = ch[k]; ihh = hd[k];
                    d0 = dv[k]; d1 = dv[k + 1];
                }
            }

            const float idl   = ihh / ibw;
            const float theta = (xc - icw) / ibw;
            const float th2   = theta * theta;
            const float tt    = theta * (1.f - theta);
            const float numer = ihh * (idl * th2 + d0 * tt);
            const float denom = idl + (d0 + d1 - 2.f * idl) * tt;
            const float zin   = ich + numer / denom;
            const float omt   = 1.f - theta;
            const float dnum  = idl * idl * (d1 * th2 + 2.f * idl * tt + d0 * omt * omt);
            const float ladv  = __logf(dnum) - 2.f * __logf(denom);

            const bool inside = (xv >= -1.f) && (xv <= 1.f);
            out[((b * C_ + c) * HW) + y * WW + x0 + m] = inside ? zin : xv;
            ladsum += inside ? ladv : 0.f;
        }
    }

    // ---- deterministic block reduction of ladsum ----
    #pragma unroll
    for (int off = 16; off; off >>= 1)
        ladsum += __shfl_down_sync(0xffffffffu, ladsum, off);
    if (lane == 0) s_wr[wid] = ladsum;
    __syncthreads();
    if (tid == 0) {
        float s = 0.f;
        #pragma unroll
        for (int i = 0; i < 8; i++) s += s_wr[i];
        g_partial[(b * HH + y) * 2 + blockIdx.x] = s;
    }
}

// =========================================================================
// deterministic reduction of partials -> logabsdet[b]
// =========================================================================
__global__ void __launch_bounds__(256) reduce_kernel(float* __restrict__ out)
{
    const int b = blockIdx.x;
    const int tid = threadIdx.x;
    __shared__ double sd[256];
    double s = (double)g_partial[b * 512 + tid]
             + (double)g_partial[b * 512 + tid + 256];
    sd[tid] = s;
    __syncthreads();
    for (int off = 128; off; off >>= 1) {
        if (tid < off) sd[tid] += sd[tid + off];
        __syncthreads();
    }
    if (tid == 0) out[B_ * C_ * HW + b] = (float)sd[0];
}

// =========================================================================
extern "C" void kernel_launch(void* const* d_in, const int* in_sizes, int n_in,
                              void* d_out, int out_size)
{
    const float* x     = (const float*)d_in[0];
    const float* clean = (const float*)d_in[1];
    const float* W1    = (const float*)d_in[2];
    const float* b1    = (const float*)d_in[3];
    const float* W2    = (const float*)d_in[4];
    const float* b2    = (const float*)d_in[5];
    float* out = (float*)d_out;

    cudaFuncSetAttribute(conv2_fused_kernel,
                         cudaFuncAttributeMaxDynamicSharedMemorySize, SMEM_TC);

    conv1_kernel<<<dim3(256, 16, 16), 256>>>(clean, W1, b1);
    prep_w_kernel<<<144, 256>>>(W2);
    conv2_fused_kernel<<<dim3(2, 256, 16), 256, SMEM_TC>>>(b2, x, out);
    reduce_kernel<<<16, 256>>>(out);
}

// round 8
// speedup vs baseline: 4.7166x; 1.0057x over previous
#include <cuda_runtime.h>
#include <cuda_bf16.h>
#include <cstdint>

#define B_   16
#define C_   4
#define HH   256
#define WW   256
#define HID  64
#define PCH  116          // C_*(3*10-1)
#define HW   (HH*WW)      // 65536

// ---------------- device scratch (no allocations allowed) ----------------
// hid stored pre-split as packed bf16x2, ic-contiguous per pixel:
// g_hidHi[((b*HH+y)*WW+x)*32 + p] packs ic = 2p (low), 2p+1 (high)
__device__ __align__(16) uint32_t g_hidHi[B_ * HW * 32];   // 134 MB
__device__ __align__(16) uint32_t g_hidLo[B_ * HW * 32];   // 134 MB
__device__ float g_partial[B_ * HH * 2];
// W2 pre-packed into exact mma.m16n8k16 B-fragment layout, bf16 hi/lo:
__device__ __align__(16) uint32_t g_WfHi[9 * 4 * 16 * 64];
__device__ __align__(16) uint32_t g_WfLo[9 * 4 * 16 * 64];

// ======================= helpers =====================
__device__ __forceinline__ uint32_t smem_to_u32(const void* p) {
    uint32_t a;
    asm("{ .reg .u64 t; cvta.to.shared.u64 t, %1; cvt.u32.u64 %0, t; }"
        : "=r"(a) : "l"(p));
    return a;
}
#define SMEM_SWIZZLE_128B(o) ((o) ^ (((o) >> 3) & 0x70))

#define STS128(r0, r1, r2, r3, a) \
    asm volatile("st.shared.v4.b32 [%0], {%1, %2, %3, %4};" \
        :: "r"(a), "r"(r0), "r"(r1), "r"(r2), "r"(r3) : "memory")

__device__ __forceinline__ void ldsm_x4(uint32_t* r, uint32_t addr) {
    asm volatile("ldmatrix.sync.aligned.m8n8.x4.shared.b16 {%0,%1,%2,%3}, [%4];"
        : "=r"(r[0]), "=r"(r[1]), "=r"(r[2]), "=r"(r[3]) : "r"(addr));
}
__device__ __forceinline__ void mma_bf16(float* d, const uint32_t* a,
                                         const uint32_t* b) {
    asm volatile(
        "mma.sync.aligned.m16n8k16.row.col.f32.bf16.bf16.f32 "
        "{%0,%1,%2,%3}, {%4,%5,%6,%7}, {%8,%9}, {%0,%1,%2,%3};"
        : "+f"(d[0]), "+f"(d[1]), "+f"(d[2]), "+f"(d[3])
        : "r"(a[0]), "r"(a[1]), "r"(a[2]), "r"(a[3]),
          "r"(b[0]), "r"(b[1]));
}

// =========================================================================
// conv1: clean -> relu(conv3x3) -> bf16 hi/lo split, ic-contiguous store.
// Block = one row y of one batch. Thread = one pixel, all 64 oc in regs.
// =========================================================================
__global__ void __launch_bounds__(256) conv1_kernel(
    const float* __restrict__ clean,
    const float* __restrict__ W1,
    const float* __restrict__ b1)
{
    __shared__ float s_w[36 * 64];        // [k][oc]
    __shared__ float s_bias[64];
    __shared__ float s_in[4][3][264];     // [ic][ky][x+1], halo, padded

    const int y = blockIdx.x;
    const int b = blockIdx.y;
    const int tid = threadIdx.x;

    for (int i = tid; i < 2304; i += 256) {
        const int oc = i & 63, k = i >> 6;
        s_w[k * 64 + oc] = W1[oc * 36 + k];
    }
    if (tid < 64) s_bias[tid] = b1[tid];
    for (int i = tid; i < 4 * 3 * 264; i += 256) {
        const int c = i / 792, rem = i - c * 792;
        const int r = rem / 264, xc = rem - r * 264;
        const int yy = y + r - 1, xx = xc - 1;
        float v = 0.f;
        if (xc < 258 && (unsigned)yy < 256u && (unsigned)xx < 256u)
            v = clean[((b * 4 + c) * HW) + yy * WW + xx];
        s_in[c][r][xc] = v;
    }
    __syncthreads();

    float acc[64];
    #pragma unroll
    for (int oc = 0; oc < 64; ++oc) acc[oc] = s_bias[oc];

    const int x = tid;
    for (int ic = 0; ic < 4; ++ic)
        for (int ky = 0; ky < 3; ++ky) {
            const float* rowp = &s_in[ic][ky][x];
            #pragma unroll
            for (int kx = 0; kx < 3; ++kx) {
                const float v = rowp[kx];
                const float4* wp = (const float4*)&s_w[(ic * 9 + ky * 3 + kx) * 64];
                #pragma unroll
                for (int o4 = 0; o4 < 16; ++o4) {
                    const float4 w = wp[o4];
                    acc[o4 * 4 + 0] = fmaf(v, w.x, acc[o4 * 4 + 0]);
                    acc[o4 * 4 + 1] = fmaf(v, w.y, acc[o4 * 4 + 1]);
                    acc[o4 * 4 + 2] = fmaf(v, w.z, acc[o4 * 4 + 2]);
                    acc[o4 * 4 + 3] = fmaf(v, w.w, acc[o4 * 4 + 3]);
                }
            }
        }

    // ReLU + bf16 hi/lo split (packed: low half = even oc)
    uint32_t hi[32], lo[32];
    #pragma unroll
    for (int p = 0; p < 32; ++p) {
        const float a0 = fmaxf(acc[2 * p], 0.f);
        const float a1 = fmaxf(acc[2 * p + 1], 0.f);
        asm("cvt.rn.bf16x2.f32 %0, %1, %2;" : "=r"(hi[p]) : "f"(a1), "f"(a0));
        const float f0 = __uint_as_float(hi[p] << 16);
        const float f1 = __uint_as_float(hi[p] & 0xffff0000u);
        asm("cvt.rn.bf16x2.f32 %0, %1, %2;" : "=r"(lo[p]) : "f"(a1 - f1), "f"(a0 - f0));
    }
    const size_t px = (size_t)(b * HH + y) * WW + x;
    uint4* dh = (uint4*)&g_hidHi[px * 32];
    uint4* dl = (uint4*)&g_hidLo[px * 32];
    #pragma unroll
    for (int q = 0; q < 8; ++q) {
        dh[q] = make_uint4(hi[q * 4], hi[q * 4 + 1], hi[q * 4 + 2], hi[q * 4 + 3]);
        dl[q] = make_uint4(lo[q * 4], lo[q * 4 + 1], lo[q * 4 + 2], lo[q * 4 + 3]);
    }
}

// =========================================================================
// prep_w: pack W2 into mma B-fragment layout (bf16 hi/lo split).
// =========================================================================
__global__ void __launch_bounds__(256) prep_w_kernel(const float* __restrict__ W2)
{
    const int i = blockIdx.x * 256 + threadIdx.x;   // over 36864
    if (i >= 9 * 4 * 16 * 64) return;
    const int r    = i & 1;
    const int lane = (i >> 1) & 31;
    const int nt   = (i >> 6) & 15;
    const int ks   = (i >> 10) & 3;
    const int j    = i >> 12;                       // 0..8 = ky*3+kx
    const int n    = nt * 8 + (lane >> 2);
    const int ic0  = ks * 16 + r * 8 + (lane & 3) * 2;

    float w0 = 0.f, w1 = 0.f;
    if (n < PCH) {
        w0 = W2[n * 576 + ic0 * 9 + j];
        w1 = W2[n * 576 + (ic0 + 1) * 9 + j];
    }
    __nv_bfloat16 h0 = __float2bfloat16(w0);
    __nv_bfloat16 h1 = __float2bfloat16(w1);
    float f0 = __bfloat162float(h0), f1 = __bfloat162float(h1);
    __nv_bfloat16 l0 = __float2bfloat16(w0 - f0);
    __nv_bfloat16 l1 = __float2bfloat16(w1 - f1);
    uint16_t uh0 = *(uint16_t*)&h0, uh1 = *(uint16_t*)&h1;
    uint16_t ul0 = *(uint16_t*)&l0, ul1 = *(uint16_t*)&l1;
    g_WfHi[i] = (uint32_t)uh0 | ((uint32_t)uh1 << 16);
    g_WfLo[i] = (uint32_t)ul0 | ((uint32_t)ul1 << 16);
}

// =========================================================================
// fused conv2 (HMMA bf16 3-pass) + bias + spline + lad partial reduction.
// A-build is now a pure copy of pre-split bf16 planes (no converts).
// =========================================================================
#define ABUF_B   33280        // 130*128 hi + pad; lo at +16640
#define SMEM_TC  67840

__device__ __forceinline__ float softplus_fast(float t) {
    return fmaxf(t, 0.f) + __logf(1.f + __expf(-fabsf(t)));
}

__global__ void __launch_bounds__(256) conv2_fused_kernel(
    const float* __restrict__ b2,
    const float* __restrict__ xin,
    float* __restrict__ out)
{
    extern __shared__ char smem[];
    __shared__ float s_b2[128];
    __shared__ float s_wr[8];
    const uint32_t sb = smem_to_u32(smem);
    const int tid = threadIdx.x, wid = tid >> 5, lane = tid & 31;
    const int x0 = blockIdx.x * 128;
    const int y  = blockIdx.y;
    const int b  = blockIdx.z;
    const int mg = wid & 1;          // m-group (64 rows)
    const int ng = wid >> 1;         // n-group (32 cols)

    if (tid < 128) s_b2[tid] = (tid < PCH) ? b2[tid] : 0.f;

    float d[4][4][4];
    #pragma unroll
    for (int mt = 0; mt < 4; ++mt)
        #pragma unroll
        for (int nt = 0; nt < 4; ++nt)
            #pragma unroll
            for (int r = 0; r < 4; ++r) d[mt][nt][r] = 0.f;

    for (int ky = 0; ky < 3; ++ky) {
        const uint32_t aHi = sb + (ky & 1) * ABUF_B;
        const uint32_t aLo = aHi + 16640;

        // ---- build A rows mm=0..129 (x=x0+mm-1): straight bf16 copy ----
        {
            const int yy  = y + ky - 1;
            const bool yok = ((unsigned)yy < 256u);
            #pragma unroll 2
            for (int i = tid; i < 130 * 4; i += 256) {
                const int mm = i >> 2, q = i & 3;
                const int xx = x0 + mm - 1;
                const bool ok = yok && ((unsigned)xx < 256u);
                uint4 vh0 = {0,0,0,0}, vh1 = {0,0,0,0};
                uint4 vl0 = {0,0,0,0}, vl1 = {0,0,0,0};
                if (ok) {
                    const size_t px = (size_t)(b * HH + yy) * WW + xx;
                    const uint4* ph = (const uint4*)&g_hidHi[px * 32 + q * 8];
                    const uint4* pl = (const uint4*)&g_hidLo[px * 32 + q * 8];
                    vh0 = ph[0]; vh1 = ph[1];
                    vl0 = pl[0]; vl1 = pl[1];
                }
                const uint32_t o0 = SMEM_SWIZZLE_128B((uint32_t)(mm * 128 + q * 32));
                const uint32_t o1 = SMEM_SWIZZLE_128B((uint32_t)(mm * 128 + q * 32 + 16));
                STS128(vh0.x, vh0.y, vh0.z, vh0.w, aHi + o0);
                STS128(vh1.x, vh1.y, vh1.z, vh1.w, aHi + o1);
                STS128(vl0.x, vl0.y, vl0.z, vl0.w, aLo + o0);
                STS128(vl1.x, vl1.y, vl1.z, vl1.w, aLo + o1);
            }
        }
        __syncthreads();

        // ---- consume: 3 kx chunks x 4 K-steps ----
        for (int kx = 0; kx < 3; ++kx) {
            const int j = ky * 3 + kx;
            #pragma unroll
            for (int ks = 0; ks < 4; ++ks) {
                uint32_t ah[4][4], al[4][4];
                const uint32_t cbyte = ks * 32 + (lane >> 4) * 16;
                #pragma unroll
                for (int mt = 0; mt < 4; ++mt) {
                    const uint32_t row =
                        (uint32_t)(mg * 64 + mt * 16 + (lane & 15) + kx);
                    const uint32_t off = SMEM_SWIZZLE_128B(row * 128 + cbyte);
                    ldsm_x4(ah[mt], aHi + off);
                    ldsm_x4(al[mt], aLo + off);
                }
                uint32_t bh[4][2], bl[4][2];
                #pragma unroll
                for (int nt4 = 0; nt4 < 4; ++nt4) {
                    const int nt = ng * 4 + nt4;
                    const int idx = ((j * 4 + ks) * 16 + nt) * 32 + lane;
                    const uint2 vh = ((const uint2*)g_WfHi)[idx];
                    const uint2 vl = ((const uint2*)g_WfLo)[idx];
                    bh[nt4][0] = vh.x; bh[nt4][1] = vh.y;
                    bl[nt4][0] = vl.x; bl[nt4][1] = vl.y;
                }
                #pragma unroll
                for (int mt = 0; mt < 4; ++mt)
                    #pragma unroll
                    for (int nt4 = 0; nt4 < 4; ++nt4) {
                        mma_bf16(d[mt][nt4], ah[mt], bh[nt4]);
                        mma_bf16(d[mt][nt4], al[mt], bh[nt4]);
                        mma_bf16(d[mt][nt4], ah[mt], bl[nt4]);
                    }
            }
        }
        __syncthreads();
    }

    // ---- stage result: s_out[n=0..127][m padded 132] ----
    float* s_out = (float*)smem;
    #pragma unroll
    for (int mt = 0; mt < 4; ++mt)
        #pragma unroll
        for (int nt4 = 0; nt4 < 4; ++nt4)
            #pragma unroll
            for (int r = 0; r < 4; ++r) {
                const int m = mg * 64 + mt * 16 + (lane >> 2) + ((r >> 1) * 8);
                const int n = ng * 32 + nt4 * 8 + (lane & 3) * 2 + (r & 1);
                s_out[n * 132 + m] = d[mt][nt4][r];
            }
    __syncthreads();

    // ---- fused spline ----
    float ladsum = 0.f;
    {
        const int m  = tid & 127;
        const int c0 = tid >> 7;
        #pragma unroll
        for (int e = 0; e < 2; ++e) {
            const int c = c0 + 2 * e;
            float pv[29];
            #pragma unroll
            for (int j = 0; j < 29; j++)
                pv[j] = s_out[(c * 29 + j) * 132 + m] + s_b2[c * 29 + j];

            const float xv = xin[((b * C_ + c) * HW) + y * WW + x0 + m];

            float uw[10];
            #pragma unroll
            for (int j = 0; j < 10; j++) uw[j] = pv[j] * 0.125f;
            float mw = uw[0];
            #pragma unroll
            for (int j = 1; j < 10; j++) mw = fmaxf(mw, uw[j]);
            float ew[10]; float ssum = 0.f;
            #pragma unroll
            for (int j = 0; j < 10; j++) { ew[j] = __expf(uw[j] - mw); ssum += ew[j]; }
            float inv = 1.0f / ssum;
            float cw[11]; cw[0] = -1.f;
            {
                float acc = 0.f;
                #pragma unroll
                for (int j = 0; j < 10; j++) {
                    float wj = fmaf(0.99f * inv, ew[j], 0.001f);
                    acc += wj;
                    cw[j + 1] = fmaf(2.f, acc, -1.f);
                }
            }
            cw[10] = 1.f;
            float wd[10];
            #pragma unroll
            for (int j = 0; j < 10; j++) wd[j] = cw[j + 1] - cw[j];

            float uh[10];
            #pragma unroll
            for (int j = 0; j < 10; j++) uh[j] = pv[10 + j] * 0.125f;
            float mh = uh[0];
            #pragma unroll
            for (int j = 1; j < 10; j++) mh = fmaxf(mh, uh[j]);
            float eh[10]; float hsum = 0.f;
            #pragma unroll
            for (int j = 0; j < 10; j++) { eh[j] = __expf(uh[j] - mh); hsum += eh[j]; }
            float hinv = 1.0f / hsum;
            float ch[11]; ch[0] = -1.f;
            {
                float acc = 0.f;
                #pragma unroll
                for (int j = 0; j < 10; j++) {
                    float hj = fmaf(0.99f * hinv, eh[j], 0.001f);
                    acc += hj;
                    ch[j + 1] = fmaf(2.f, acc, -1.f);
                }
            }
            ch[10] = 1.f;
            float hd[10];
            #pragma unroll
            for (int j = 0; j < 10; j++) hd[j] = ch[j + 1] - ch[j];

            const float spc = 0.53974215f;          // log(exp(0.999)-1)
            const float dvE = 0.001f + softplus_fast(spc);
            float dv[11];
            dv[0] = dvE; dv[10] = dvE;
            #pragma unroll
            for (int j = 1; j < 10; j++) dv[j] = 0.001f + softplus_fast(pv[19 + j]);

            const float xc = fminf(fmaxf(xv, -1.f), 1.f);
            float icw = cw[0], ibw = wd[0], ich = ch[0], ihh = hd[0];
            float d0 = dv[0], d1 = dv[1];
            #pragma unroll
            for (int k = 1; k < 10; k++) {
                if (xc >= cw[k]) {
                    icw = cw[k]; ibw = wd[k]; ich = ch[k]; ihh = hd[k];
                    d0 = dv[k]; d1 = dv[k + 1];
                }
            }

            const float idl   = ihh / ibw;
            const float theta = (xc - icw) / ibw;
            const float th2   = theta * theta;
            const float tt    = theta * (1.f - theta);
            const float numer = ihh * (idl * th2 + d0 * tt);
            const float denom = idl + (d0 + d1 - 2.f * idl) * tt;
            const float zin   = ich + numer / denom;
            const float omt   = 1.f - theta;
            const float dnum  = idl * idl * (d1 * th2 + 2.f * idl * tt + d0 * omt * omt);
            const float ladv  = __logf(dnum) - 2.f * __logf(denom);

            const bool inside = (xv >= -1.f) && (xv <= 1.f);
            out[((b * C_ + c) * HW) + y * WW + x0 + m] = inside ? zin : xv;
            ladsum += inside ? ladv : 0.f;
        }
    }

    // ---- deterministic block reduction of ladsum ----
    #pragma unroll
    for (int off = 16; off; off >>= 1)
        ladsum += __shfl_down_sync(0xffffffffu, ladsum, off);
    if (lane == 0) s_wr[wid] = ladsum;
    __syncthreads();
    if (tid == 0) {
        float s = 0.f;
        #pragma unroll
        for (int i = 0; i < 8; i++) s += s_wr[i];
        g_partial[(b * HH + y) * 2 + blockIdx.x] = s;
    }
}

// =========================================================================
// deterministic reduction of partials -> logabsdet[b]
// =========================================================================
__global__ void __launch_bounds__(256) reduce_kernel(float* __restrict__ out)
{
    const int b = blockIdx.x;
    const int tid = threadIdx.x;
    __shared__ double sd[256];
    double s = (double)g_partial[b * 512 + tid]
             + (double)g_partial[b * 512 + tid + 256];
    sd[tid] = s;
    __syncthreads();
    for (int off = 128; off; off >>= 1) {
        if (tid < off) sd[tid] += sd[tid + off];
        __syncthreads();
    }
    if (tid == 0) out[B_ * C_ * HW + b] = (float)sd[0];
}

// =========================================================================
extern "C" void kernel_launch(void* const* d_in, const int* in_sizes, int n_in,
                              void* d_out, int out_size)
{
    const float* x     = (const float*)d_in[0];
    const float* clean = (const float*)d_in[1];
    const float* W1    = (const float*)d_in[2];
    const float* b1    = (const float*)d_in[3];
    const float* W2    = (const float*)d_in[4];
    const float* b2    = (const float*)d_in[5];
    float* out = (float*)d_out;

    cudaFuncSetAttribute(conv2_fused_kernel,
                         cudaFuncAttributeMaxDynamicSharedMemorySize, SMEM_TC);

    conv1_kernel<<<dim3(256, 16), 256>>>(clean, W1, b1);
    prep_w_kernel<<<144, 256>>>(W2);
    conv2_fused_kernel<<<dim3(2, 256, 16), 256, SMEM_TC>>>(b2, x, out);
    reduce_kernel<<<16, 256>>>(out);
}

// round 9
// speedup vs baseline: 4.8998x; 1.0388x over previous
#include <cuda_runtime.h>
#include <cuda_fp16.h>
#include <cstdint>

#define B_   16
#define C_   4
#define HH   256
#define WW   256
#define HID  64
#define PCH  116          // C_*(3*10-1)
#define HW   (HH*WW)      // 65536

// ---------------- device scratch (no allocations allowed) ----------------
// hid as packed fp16x2, ic-contiguous per pixel: g_hidF[px*32 + p] = ic 2p,2p+1
__device__ __align__(16) uint32_t g_hidF[B_ * HW * 32];    // 134 MB
__device__ float g_partial[B_ * HH * 2];
// W2 in mma.m16n8k16 B-fragment layout, fp16 hi/lo
__device__ __align__(16) uint32_t g_WfHi[9 * 4 * 16 * 64];
__device__ __align__(16) uint32_t g_WfLo[9 * 4 * 16 * 64];

// ======================= helpers =====================
__device__ __forceinline__ uint32_t smem_to_u32(const void* p) {
    uint32_t a;
    asm("{ .reg .u64 t; cvta.to.shared.u64 t, %1; cvt.u32.u64 %0, t; }"
        : "=r"(a) : "l"(p));
    return a;
}
#define SMEM_SWIZZLE_128B(o) ((o) ^ (((o) >> 3) & 0x70))

#define STS128(r0, r1, r2, r3, a) \
    asm volatile("st.shared.v4.b32 [%0], {%1, %2, %3, %4};" \
        :: "r"(a), "r"(r0), "r"(r1), "r"(r2), "r"(r3) : "memory")

__device__ __forceinline__ void ldsm_x4(uint32_t* r, uint32_t addr) {
    asm volatile("ldmatrix.sync.aligned.m8n8.x4.shared.b16 {%0,%1,%2,%3}, [%4];"
        : "=r"(r[0]), "=r"(r[1]), "=r"(r[2]), "=r"(r[3]) : "r"(addr));
}
__device__ __forceinline__ void mma_f16(float* d, const uint32_t* a,
                                        const uint32_t* b) {
    asm volatile(
        "mma.sync.aligned.m16n8k16.row.col.f32.f16.f16.f32 "
        "{%0,%1,%2,%3}, {%4,%5,%6,%7}, {%8,%9}, {%0,%1,%2,%3};"
        : "+f"(d[0]), "+f"(d[1]), "+f"(d[2]), "+f"(d[3])
        : "r"(a[0]), "r"(a[1]), "r"(a[2]), "r"(a[3]),
          "r"(b[0]), "r"(b[1]));
}

// =========================================================================
// conv1: clean -> relu(conv3x3) -> fp16 pack, ic-contiguous store.
// =========================================================================
__global__ void __launch_bounds__(256) conv1_kernel(
    const float* __restrict__ clean,
    const float* __restrict__ W1,
    const float* __restrict__ b1)
{
    __shared__ float s_w[36 * 64];
    __shared__ float s_bias[64];
    __shared__ float s_in[4][3][264];

    const int y = blockIdx.x;
    const int b = blockIdx.y;
    const int tid = threadIdx.x;

    for (int i = tid; i < 2304; i += 256) {
        const int oc = i & 63, k = i >> 6;
        s_w[k * 64 + oc] = W1[oc * 36 + k];
    }
    if (tid < 64) s_bias[tid] = b1[tid];
    for (int i = tid; i < 4 * 3 * 264; i += 256) {
        const int c = i / 792, rem = i - c * 792;
        const int r = rem / 264, xc = rem - r * 264;
        const int yy = y + r - 1, xx = xc - 1;
        float v = 0.f;
        if (xc < 258 && (unsigned)yy < 256u && (unsigned)xx < 256u)
            v = clean[((b * 4 + c) * HW) + yy * WW + xx];
        s_in[c][r][xc] = v;
    }
    __syncthreads();

    float acc[64];
    #pragma unroll
    for (int oc = 0; oc < 64; ++oc) acc[oc] = s_bias[oc];

    const int x = tid;
    for (int ic = 0; ic < 4; ++ic)
        for (int ky = 0; ky < 3; ++ky) {
            const float* rowp = &s_in[ic][ky][x];
            #pragma unroll
            for (int kx = 0; kx < 3; ++kx) {
                const float v = rowp[kx];
                const float4* wp = (const float4*)&s_w[(ic * 9 + ky * 3 + kx) * 64];
                #pragma unroll
                for (int o4 = 0; o4 < 16; ++o4) {
                    const float4 w = wp[o4];
                    acc[o4 * 4 + 0] = fmaf(v, w.x, acc[o4 * 4 + 0]);
                    acc[o4 * 4 + 1] = fmaf(v, w.y, acc[o4 * 4 + 1]);
                    acc[o4 * 4 + 2] = fmaf(v, w.z, acc[o4 * 4 + 2]);
                    acc[o4 * 4 + 3] = fmaf(v, w.w, acc[o4 * 4 + 3]);
                }
            }
        }

    uint32_t hp[32];
    #pragma unroll
    for (int p = 0; p < 32; ++p) {
        const float a0 = fmaxf(acc[2 * p], 0.f);
        const float a1 = fmaxf(acc[2 * p + 1], 0.f);
        const __half2 hh = __floats2half2_rn(a0, a1);
        hp[p] = *(const uint32_t*)&hh;
    }
    const size_t px = (size_t)(b * HH + y) * WW + x;
    uint4* dh = (uint4*)&g_hidF[px * 32];
    #pragma unroll
    for (int q = 0; q < 8; ++q)
        dh[q] = make_uint4(hp[q * 4], hp[q * 4 + 1], hp[q * 4 + 2], hp[q * 4 + 3]);
}

// =========================================================================
// prep_w: pack W2 into mma B-fragment layout, fp16 hi/lo split.
// =========================================================================
__global__ void __launch_bounds__(256) prep_w_kernel(const float* __restrict__ W2)
{
    const int i = blockIdx.x * 256 + threadIdx.x;
    if (i >= 9 * 4 * 16 * 64) return;
    const int r    = i & 1;
    const int lane = (i >> 1) & 31;
    const int nt   = (i >> 6) & 15;
    const int ks   = (i >> 10) & 3;
    const int j    = i >> 12;
    const int n    = nt * 8 + (lane >> 2);
    const int ic0  = ks * 16 + r * 8 + (lane & 3) * 2;

    float w0 = 0.f, w1 = 0.f;
    if (n < PCH) {
        w0 = W2[n * 576 + ic0 * 9 + j];
        w1 = W2[n * 576 + (ic0 + 1) * 9 + j];
    }
    const __half h0 = __float2half_rn(w0), h1 = __float2half_rn(w1);
    const __half l0 = __float2half_rn(w0 - __half2float(h0));
    const __half l1 = __float2half_rn(w1 - __half2float(h1));
    const uint16_t uh0 = *(const uint16_t*)&h0, uh1 = *(const uint16_t*)&h1;
    const uint16_t ul0 = *(const uint16_t*)&l0, ul1 = *(const uint16_t*)&l1;
    g_WfHi[i] = (uint32_t)uh0 | ((uint32_t)uh1 << 16);
    g_WfLo[i] = (uint32_t)ul0 | ((uint32_t)ul1 << 16);
}

// =========================================================================
// fused conv2 (HMMA fp16 2-pass) + bias + spline + lad reduction.
// 512 threads, 16 warps: warp tile 32(m) x 32(n). Single A buffer +
// register-prefetch pipeline across the 3 ky chunks.
// =========================================================================
#define SMEM_TC  61440     // max(A buf 16640, s_out 116*132*4 = 61248)

__device__ __forceinline__ float softplus_fast(float t) {
    return fmaxf(t, 0.f) + __logf(1.f + __expf(-fabsf(t)));
}

__device__ __forceinline__ uint4 ld_gran(int b, int yy, int x0, int g) {
    const int mm = g >> 3, q = g & 7;
    const int xx = x0 + mm - 1;
    uint4 v = make_uint4(0, 0, 0, 0);
    if ((unsigned)yy < 256u && (unsigned)xx < 256u)
        v = *(const uint4*)&g_hidF[((size_t)(b * HH + yy) * WW + xx) * 32 + q * 4];
    return v;
}

__global__ void __launch_bounds__(512) conv2_fused_kernel(
    const float* __restrict__ b2,
    const float* __restrict__ xin,
    float* __restrict__ out)
{
    extern __shared__ char smem[];
    __shared__ float s_b2[128];
    __shared__ float s_wr[16];
    const uint32_t sb = smem_to_u32(smem);
    const int tid = threadIdx.x, wid = tid >> 5, lane = tid & 31;
    const int x0 = blockIdx.x * 128;
    const int y  = blockIdx.y;
    const int b  = blockIdx.z;
    const int mg = wid & 3;          // m-group (32 rows)
    const int ng = wid >> 2;         // n-group (32 cols)

    if (tid < 128) s_b2[tid] = (tid < PCH) ? b2[tid] : 0.f;

    float d[2][4][4];
    #pragma unroll
    for (int mt = 0; mt < 2; ++mt)
        #pragma unroll
        for (int nt = 0; nt < 4; ++nt)
            #pragma unroll
            for (int r = 0; r < 4; ++r) d[mt][nt][r] = 0.f;

    // prefetch ky=0 (yy = y-1)
    uint4 pf0 = ld_gran(b, y - 1, x0, tid);
    uint4 pf1 = ld_gran(b, y - 1, x0, tid + 512);
    uint4 pf2 = (tid < 16) ? ld_gran(b, y - 1, x0, tid + 1024)
                           : make_uint4(0, 0, 0, 0);

    for (int ky = 0; ky < 3; ++ky) {
        // ---- store prefetched granules (SW128) ----
        {
            const int g0 = tid;
            STS128(pf0.x, pf0.y, pf0.z, pf0.w,
                   sb + SMEM_SWIZZLE_128B((uint32_t)((g0 >> 3) * 128 + (g0 & 7) * 16)));
            const int g1 = tid + 512;
            STS128(pf1.x, pf1.y, pf1.z, pf1.w,
                   sb + SMEM_SWIZZLE_128B((uint32_t)((g1 >> 3) * 128 + (g1 & 7) * 16)));
            if (tid < 16) {
                const int g2 = tid + 1024;
                STS128(pf2.x, pf2.y, pf2.z, pf2.w,
                       sb + SMEM_SWIZZLE_128B((uint32_t)((g2 >> 3) * 128 + (g2 & 7) * 16)));
            }
        }
        __syncthreads();

        // ---- prefetch next ky while MMAs run ----
        if (ky < 2) {
            pf0 = ld_gran(b, y + ky, x0, tid);
            pf1 = ld_gran(b, y + ky, x0, tid + 512);
            if (tid < 16) pf2 = ld_gran(b, y + ky, x0, tid + 1024);
        }

        // ---- consume: 3 kx chunks x 4 K-steps ----
        for (int kx = 0; kx < 3; ++kx) {
            const int j = ky * 3 + kx;
            #pragma unroll
            for (int ks = 0; ks < 4; ++ks) {
                uint32_t ah[2][4];
                const uint32_t cbyte = ks * 32 + (lane >> 4) * 16;
                #pragma unroll
                for (int mt = 0; mt < 2; ++mt) {
                    const uint32_t row =
                        (uint32_t)(mg * 32 + mt * 16 + (lane & 15) + kx);
                    ldsm_x4(ah[mt], sb + SMEM_SWIZZLE_128B(row * 128 + cbyte));
                }
                uint32_t bh[4][2], bl[4][2];
                #pragma unroll
                for (int nt4 = 0; nt4 < 4; ++nt4) {
                    const int nt = ng * 4 + nt4;
                    const int idx = ((j * 4 + ks) * 16 + nt) * 32 + lane;
                    const uint2 vh = ((const uint2*)g_WfHi)[idx];
                    const uint2 vl = ((const uint2*)g_WfLo)[idx];
                    bh[nt4][0] = vh.x; bh[nt4][1] = vh.y;
                    bl[nt4][0] = vl.x; bl[nt4][1] = vl.y;
                }
                #pragma unroll
                for (int mt = 0; mt < 2; ++mt)
                    #pragma unroll
                    for (int nt4 = 0; nt4 < 4; ++nt4) {
                        mma_f16(d[mt][nt4], ah[mt], bh[nt4]);
                        mma_f16(d[mt][nt4], ah[mt], bl[nt4]);
                    }
            }
        }
        __syncthreads();
    }

    // ---- stage result: s_out[n=0..115][m padded 132] ----
    float* s_out = (float*)smem;
    #pragma unroll
    for (int mt = 0; mt < 2; ++mt)
        #pragma unroll
        for (int nt4 = 0; nt4 < 4; ++nt4)
            #pragma unroll
            for (int r = 0; r < 4; ++r) {
                const int m = mg * 32 + mt * 16 + (lane >> 2) + ((r >> 1) * 8);
                const int n = ng * 32 + nt4 * 8 + (lane & 3) * 2 + (r & 1);
                if (n < PCH) s_out[n * 132 + m] = d[mt][nt4][r];
            }
    __syncthreads();

    // ---- fused spline: thread = one (c, pixel) ----
    float ladsum = 0.f;
    {
        const int m = tid & 127;
        const int c = tid >> 7;
        float pv[29];
        #pragma unroll
        for (int j = 0; j < 29; j++)
            pv[j] = s_out[(c * 29 + j) * 132 + m] + s_b2[c * 29 + j];

        const float xv = xin[((b * C_ + c) * HW) + y * WW + x0 + m];

        float uw[10];
        #pragma unroll
        for (int j = 0; j < 10; j++) uw[j] = pv[j] * 0.125f;
        float mw = uw[0];
        #pragma unroll
        for (int j = 1; j < 10; j++) mw = fmaxf(mw, uw[j]);
        float ew[10]; float ssum = 0.f;
        #pragma unroll
        for (int j = 0; j < 10; j++) { ew[j] = __expf(uw[j] - mw); ssum += ew[j]; }
        float inv = 1.0f / ssum;
        float cw[11]; cw[0] = -1.f;
        {
            float acc = 0.f;
            #pragma unroll
            for (int j = 0; j < 10; j++) {
                float wj = fmaf(0.99f * inv, ew[j], 0.001f);
                acc += wj;
                cw[j + 1] = fmaf(2.f, acc, -1.f);
            }
        }
        cw[10] = 1.f;
        float wd[10];
        #pragma unroll
        for (int j = 0; j < 10; j++) wd[j] = cw[j + 1] - cw[j];

        float uh[10];
        #pragma unroll
        for (int j = 0; j < 10; j++) uh[j] = pv[10 + j] * 0.125f;
        float mh = uh[0];
        #pragma unroll
        for (int j = 1; j < 10; j++) mh = fmaxf(mh, uh[j]);
        float eh[10]; float hsum = 0.f;
        #pragma unroll
        for (int j = 0; j < 10; j++) { eh[j] = __expf(uh[j] - mh); hsum += eh[j]; }
        float hinv = 1.0f / hsum;
        float ch[11]; ch[0] = -1.f;
        {
            float acc = 0.f;
            #pragma unroll
            for (int j = 0; j < 10; j++) {
                float hj = fmaf(0.99f * hinv, eh[j], 0.001f);
                acc += hj;
                ch[j + 1] = fmaf(2.f, acc, -1.f);
            }
        }
        ch[10] = 1.f;
        float hd[10];
        #pragma unroll
        for (int j = 0; j < 10; j++) hd[j] = ch[j + 1] - ch[j];

        const float spc = 0.53974215f;          // log(exp(0.999)-1)
        const float dvE = 0.001f + softplus_fast(spc);
        float dv[11];
        dv[0] = dvE; dv[10] = dvE;
        #pragma unroll
        for (int j = 1; j < 10; j++) dv[j] = 0.001f + softplus_fast(pv[19 + j]);

        const float xc = fminf(fmaxf(xv, -1.f), 1.f);
        float icw = cw[0], ibw = wd[0], ich = ch[0], ihh = hd[0];
        float d0 = dv[0], d1 = dv[1];
        #pragma unroll
        for (int k = 1; k < 10; k++) {
            if (xc >= cw[k]) {
                icw = cw[k]; ibw = wd[k]; ich = ch[k]; ihh = hd[k];
                d0 = dv[k]; d1 = dv[k + 1];
            }
        }

        const float idl   = ihh / ibw;
        const float theta = (xc - icw) / ibw;
        const float th2   = theta * theta;
        const float tt    = theta * (1.f - theta);
        const float numer = ihh * (idl * th2 + d0 * tt);
        const float denom = idl + (d0 + d1 - 2.f * idl) * tt;
        const float zin   = ich + numer / denom;
        const float omt   = 1.f - theta;
        const float dnum  = idl * idl * (d1 * th2 + 2.f * idl * tt + d0 * omt * omt);
        const float ladv  = __logf(dnum) - 2.f * __logf(denom);

        const bool inside = (xv >= -1.f) && (xv <= 1.f);
        out[((b * C_ + c) * HW) + y * WW + x0 + m] = inside ? zin : xv;
        ladsum = inside ? ladv : 0.f;
    }

    // ---- deterministic block reduction of ladsum ----
    #pragma unroll
    for (int off = 16; off; off >>= 1)
        ladsum += __shfl_down_sync(0xffffffffu, ladsum, off);
    if (lane == 0) s_wr[wid] = ladsum;
    __syncthreads();
    if (tid == 0) {
        float s = 0.f;
        #pragma unroll
        for (int i = 0; i < 16; i++) s += s_wr[i];
        g_partial[(b * HH + y) * 2 + blockIdx.x] = s;
    }
}

// =========================================================================
__global__ void __launch_bounds__(256) reduce_kernel(float* __restrict__ out)
{
    const int b = blockIdx.x;
    const int tid = threadIdx.x;
    __shared__ double sd[256];
    double s = (double)g_partial[b * 512 + tid]
             + (double)g_partial[b * 512 + tid + 256];
    sd[tid] = s;
    __syncthreads();
    for (int off = 128; off; off >>= 1) {
        if (tid < off) sd[tid] += sd[tid + off];
        __syncthreads();
    }
    if (tid == 0) out[B_ * C_ * HW + b] = (float)sd[0];
}

// =========================================================================
extern "C" void kernel_launch(void* const* d_in, const int* in_sizes, int n_in,
                              void* d_out, int out_size)
{
    const float* x     = (const float*)d_in[0];
    const float* clean = (const float*)d_in[1];
    const float* W1    = (const float*)d_in[2];
    const float* b1    = (const float*)d_in[3];
    const float* W2    = (const float*)d_in[4];
    const float* b2    = (const float*)d_in[5];
    float* out = (float*)d_out;

    cudaFuncSetAttribute(conv2_fused_kernel,
                         cudaFuncAttributeMaxDynamicSharedMemorySize, SMEM_TC);

    conv1_kernel<<<dim3(256, 16), 256>>>(clean, W1, b1);
    prep_w_kernel<<<144, 256>>>(W2);
    conv2_fused_kernel<<<dim3(2, 256, 16), 512, SMEM_TC>>>(b2, x, out);
    reduce_kernel<<<16, 256>>>(out);
}

// round 10
// speedup vs baseline: 10.5998x; 2.1633x over previous
#include <cuda_runtime.h>
#include <cuda_fp16.h>
#include <cstdint>

#define B_   16
#define C_   4
#define HH   256
#define WW   256
#define HID  64
#define PCH  116          // C_*(3*10-1)
#define HW   (HH*WW)      // 65536

// ---------------- device scratch (no allocations allowed) ----------------
// hid as packed fp16x2, ic-contiguous per pixel: g_hidF[px*32 + p] = ic 2p,2p+1
__device__ __align__(16) uint32_t g_hidF[B_ * HW * 32];    // 134 MB
__device__ float g_partial[B_ * HH * 2];
// W2 in mma.m16n8k16 B-fragment layout, fp16 (single precision pass)
__device__ __align__(16) uint32_t g_WfHi[9 * 4 * 16 * 64];

// ======================= helpers =====================
__device__ __forceinline__ uint32_t smem_to_u32(const void* p) {
    uint32_t a;
    asm("{ .reg .u64 t; cvta.to.shared.u64 t, %1; cvt.u32.u64 %0, t; }"
        : "=r"(a) : "l"(p));
    return a;
}
#define SMEM_SWIZZLE_128B(o) ((o) ^ (((o) >> 3) & 0x70))

#define STS128(r0, r1, r2, r3, a) \
    asm volatile("st.shared.v4.b32 [%0], {%1, %2, %3, %4};" \
        :: "r"(a), "r"(r0), "r"(r1), "r"(r2), "r"(r3) : "memory")

__device__ __forceinline__ void ldsm_x4(uint32_t* r, uint32_t addr) {
    asm volatile("ldmatrix.sync.aligned.m8n8.x4.shared.b16 {%0,%1,%2,%3}, [%4];"
        : "=r"(r[0]), "=r"(r[1]), "=r"(r[2]), "=r"(r[3]) : "r"(addr));
}
__device__ __forceinline__ void mma_f16(float* d, const uint32_t* a,
                                        const uint32_t* b) {
    asm volatile(
        "mma.sync.aligned.m16n8k16.row.col.f32.f16.f16.f32 "
        "{%0,%1,%2,%3}, {%4,%5,%6,%7}, {%8,%9}, {%0,%1,%2,%3};"
        : "+f"(d[0]), "+f"(d[1]), "+f"(d[2]), "+f"(d[3])
        : "r"(a[0]), "r"(a[1]), "r"(a[2]), "r"(a[3]),
          "r"(b[0]), "r"(b[1]));
}

// =========================================================================
// conv1: clean -> relu(conv3x3) -> fp16 pack, ic-contiguous store.
// =========================================================================
__global__ void __launch_bounds__(256) conv1_kernel(
    const float* __restrict__ clean,
    const float* __restrict__ W1,
    const float* __restrict__ b1)
{
    __shared__ float s_w[36 * 64];
    __shared__ float s_bias[64];
    __shared__ float s_in[4][3][264];

    const int y = blockIdx.x;
    const int b = blockIdx.y;
    const int tid = threadIdx.x;

    for (int i = tid; i < 2304; i += 256) {
        const int oc = i & 63, k = i >> 6;
        s_w[k * 64 + oc] = W1[oc * 36 + k];
    }
    if (tid < 64) s_bias[tid] = b1[tid];
    for (int i = tid; i < 4 * 3 * 264; i += 256) {
        const int c = i / 792, rem = i - c * 792;
        const int r = rem / 264, xc = rem - r * 264;
        const int yy = y + r - 1, xx = xc - 1;
        float v = 0.f;
        if (xc < 258 && (unsigned)yy < 256u && (unsigned)xx < 256u)
            v = clean[((b * 4 + c) * HW) + yy * WW + xx];
        s_in[c][r][xc] = v;
    }
    __syncthreads();

    float acc[64];
    #pragma unroll
    for (int oc = 0; oc < 64; ++oc) acc[oc] = s_bias[oc];

    const int x = tid;
    for (int ic = 0; ic < 4; ++ic)
        for (int ky = 0; ky < 3; ++ky) {
            const float* rowp = &s_in[ic][ky][x];
            #pragma unroll
            for (int kx = 0; kx < 3; ++kx) {
                const float v = rowp[kx];
                const float4* wp = (const float4*)&s_w[(ic * 9 + ky * 3 + kx) * 64];
                #pragma unroll
                for (int o4 = 0; o4 < 16; ++o4) {
                    const float4 w = wp[o4];
                    acc[o4 * 4 + 0] = fmaf(v, w.x, acc[o4 * 4 + 0]);
                    acc[o4 * 4 + 1] = fmaf(v, w.y, acc[o4 * 4 + 1]);
                    acc[o4 * 4 + 2] = fmaf(v, w.z, acc[o4 * 4 + 2]);
                    acc[o4 * 4 + 3] = fmaf(v, w.w, acc[o4 * 4 + 3]);
                }
            }
        }

    uint32_t hp[32];
    #pragma unroll
    for (int p = 0; p < 32; ++p) {
        const float a0 = fmaxf(acc[2 * p], 0.f);
        const float a1 = fmaxf(acc[2 * p + 1], 0.f);
        const __half2 hh = __floats2half2_rn(a0, a1);
        hp[p] = *(const uint32_t*)&hh;
    }
    const size_t px = (size_t)(b * HH + y) * WW + x;
    uint4* dh = (uint4*)&g_hidF[px * 32];
    #pragma unroll
    for (int q = 0; q < 8; ++q)
        dh[q] = make_uint4(hp[q * 4], hp[q * 4 + 1], hp[q * 4 + 2], hp[q * 4 + 3]);
}

// =========================================================================
// prep_w: pack W2 into mma B-fragment layout, fp16.
// =========================================================================
__global__ void __launch_bounds__(256) prep_w_kernel(const float* __restrict__ W2)
{
    const int i = blockIdx.x * 256 + threadIdx.x;
    if (i >= 9 * 4 * 16 * 64) return;
    const int r    = i & 1;
    const int lane = (i >> 1) & 31;
    const int nt   = (i >> 6) & 15;
    const int ks   = (i >> 10) & 3;
    const int j    = i >> 12;
    const int n    = nt * 8 + (lane >> 2);
    const int ic0  = ks * 16 + r * 8 + (lane & 3) * 2;

    float w0 = 0.f, w1 = 0.f;
    if (n < PCH) {
        w0 = W2[n * 576 + ic0 * 9 + j];
        w1 = W2[n * 576 + (ic0 + 1) * 9 + j];
    }
    const __half h0 = __float2half_rn(w0), h1 = __float2half_rn(w1);
    const uint16_t uh0 = *(const uint16_t*)&h0, uh1 = *(const uint16_t*)&h1;
    g_WfHi[i] = (uint32_t)uh0 | ((uint32_t)uh1 << 16);
}

// =========================================================================
// fused conv2 (HMMA fp16 single-pass) + bias + spline + lad reduction.
// 256 threads, 8 warps: warp tile 64(m) x 32(n) amortizes B fragments.
// Single A buffer + register prefetch across the 3 ky chunks.
// =========================================================================
#define SMEM_TC  61440     // max(A buf 16640, s_out 116*132*4 = 61248)

__device__ __forceinline__ float softplus_fast(float t) {
    return fmaxf(t, 0.f) + __logf(1.f + __expf(-fabsf(t)));
}

__device__ __forceinline__ uint4 ld_gran(int b, int yy, int x0, int g) {
    const int mm = g >> 3, q = g & 7;
    const int xx = x0 + mm - 1;
    uint4 v = make_uint4(0, 0, 0, 0);
    if ((unsigned)yy < 256u && (unsigned)xx < 256u)
        v = *(const uint4*)&g_hidF[((size_t)(b * HH + yy) * WW + xx) * 32 + q * 4];
    return v;
}

__global__ void __launch_bounds__(256, 2) conv2_fused_kernel(
    const float* __restrict__ b2,
    const float* __restrict__ xin,
    float* __restrict__ out)
{
    extern __shared__ char smem[];
    __shared__ float s_b2[128];
    __shared__ float s_wr[8];
    const uint32_t sb = smem_to_u32(smem);
    const int tid = threadIdx.x, wid = tid >> 5, lane = tid & 31;
    const int x0 = blockIdx.x * 128;
    const int y  = blockIdx.y;
    const int b  = blockIdx.z;
    const int mg = wid & 1;          // m-group (64 rows)
    const int ng = wid >> 1;         // n-group (32 cols)

    if (tid < 128) s_b2[tid] = (tid < PCH) ? b2[tid] : 0.f;

    float d[4][4][4];
    #pragma unroll
    for (int mt = 0; mt < 4; ++mt)
        #pragma unroll
        for (int nt = 0; nt < 4; ++nt)
            #pragma unroll
            for (int r = 0; r < 4; ++r) d[mt][nt][r] = 0.f;

    // prefetch ky=0 (yy = y-1): 1040 granules = 4*256 + 16
    uint4 pf[4];
    #pragma unroll
    for (int q = 0; q < 4; ++q) pf[q] = ld_gran(b, y - 1, x0, tid + q * 256);
    uint4 pfT = (tid < 16) ? ld_gran(b, y - 1, x0, 1024 + tid)
                           : make_uint4(0, 0, 0, 0);

    for (int ky = 0; ky < 3; ++ky) {
        // ---- store prefetched granules (SW128) ----
        #pragma unroll
        for (int q = 0; q < 4; ++q) {
            const int g = tid + q * 256;
            STS128(pf[q].x, pf[q].y, pf[q].z, pf[q].w,
                   sb + SMEM_SWIZZLE_128B((uint32_t)((g >> 3) * 128 + (g & 7) * 16)));
        }
        if (tid < 16) {
            const int g = 1024 + tid;
            STS128(pfT.x, pfT.y, pfT.z, pfT.w,
                   sb + SMEM_SWIZZLE_128B((uint32_t)((g >> 3) * 128 + (g & 7) * 16)));
        }
        __syncthreads();

        // ---- prefetch next ky while MMAs run ----
        if (ky < 2) {
            #pragma unroll
            for (int q = 0; q < 4; ++q) pf[q] = ld_gran(b, y + ky, x0, tid + q * 256);
            if (tid < 16) pfT = ld_gran(b, y + ky, x0, 1024 + tid);
        }

        // ---- consume: 3 kx chunks x 4 K-steps ----
        for (int kx = 0; kx < 3; ++kx) {
            const int j = ky * 3 + kx;
            #pragma unroll
            for (int ks = 0; ks < 4; ++ks) {
                uint32_t ah[4][4];
                const uint32_t cbyte = ks * 32 + (lane >> 4) * 16;
                #pragma unroll
                for (int mt = 0; mt < 4; ++mt) {
                    const uint32_t row =
                        (uint32_t)(mg * 64 + mt * 16 + (lane & 15) + kx);
                    ldsm_x4(ah[mt], sb + SMEM_SWIZZLE_128B(row * 128 + cbyte));
                }
                uint32_t bh[4][2];
                #pragma unroll
                for (int nt4 = 0; nt4 < 4; ++nt4) {
                    const int nt = ng * 4 + nt4;
                    const int idx = ((j * 4 + ks) * 16 + nt) * 32 + lane;
                    const uint2 vh = ((const uint2*)g_WfHi)[idx];
                    bh[nt4][0] = vh.x; bh[nt4][1] = vh.y;
                }
                #pragma unroll
                for (int mt = 0; mt < 4; ++mt)
                    #pragma unroll
                    for (int nt4 = 0; nt4 < 4; ++nt4)
                        mma_f16(d[mt][nt4], ah[mt], bh[nt4]);
            }
        }
        __syncthreads();
    }

    // ---- stage result: s_out[n=0..115][m padded 132] ----
    float* s_out = (float*)smem;
    #pragma unroll
    for (int mt = 0; mt < 4; ++mt)
        #pragma unroll
        for (int nt4 = 0; nt4 < 4; ++nt4)
            #pragma unroll
            for (int r = 0; r < 4; ++r) {
                const int m = mg * 64 + mt * 16 + (lane >> 2) + ((r >> 1) * 8);
                const int n = ng * 32 + nt4 * 8 + (lane & 3) * 2 + (r & 1);
                if (n < PCH) s_out[n * 132 + m] = d[mt][nt4][r];
            }
    __syncthreads();

    // ---- fused spline: thread handles pixels m=tid&127 for c0, c0+2 ----
    float ladsum = 0.f;
    {
        const int m  = tid & 127;
        const int c0 = tid >> 7;
        #pragma unroll
        for (int e = 0; e < 2; ++e) {
            const int c = c0 + 2 * e;
            float pv[29];
            #pragma unroll
            for (int j = 0; j < 29; j++)
                pv[j] = s_out[(c * 29 + j) * 132 + m] + s_b2[c * 29 + j];

            const float xv = xin[((b * C_ + c) * HW) + y * WW + x0 + m];

            float uw[10];
            #pragma unroll
            for (int j = 0; j < 10; j++) uw[j] = pv[j] * 0.125f;
            float mw = uw[0];
            #pragma unroll
            for (int j = 1; j < 10; j++) mw = fmaxf(mw, uw[j]);
            float ew[10]; float ssum = 0.f;
            #pragma unroll
            for (int j = 0; j < 10; j++) { ew[j] = __expf(uw[j] - mw); ssum += ew[j]; }
            float inv = 1.0f / ssum;
            float cw[11]; cw[0] = -1.f;
            {
                float acc = 0.f;
                #pragma unroll
                for (int j = 0; j < 10; j++) {
                    float wj = fmaf(0.99f * inv, ew[j], 0.001f);
                    acc += wj;
                    cw[j + 1] = fmaf(2.f, acc, -1.f);
                }
            }
            cw[10] = 1.f;
            float wd[10];
            #pragma unroll
            for (int j = 0; j < 10; j++) wd[j] = cw[j + 1] - cw[j];

            float uh[10];
            #pragma unroll
            for (int j = 0; j < 10; j++) uh[j] = pv[10 + j] * 0.125f;
            float mh = uh[0];
            #pragma unroll
            for (int j = 1; j < 10; j++) mh = fmaxf(mh, uh[j]);
            float eh[10]; float hsum = 0.f;
            #pragma unroll
            for (int j = 0; j < 10; j++) { eh[j] = __expf(uh[j] - mh); hsum += eh[j]; }
            float hinv = 1.0f / hsum;
            float ch[11]; ch[0] = -1.f;
            {
                float acc = 0.f;
                #pragma unroll
                for (int j = 0; j < 10; j++) {
                    float hj = fmaf(0.99f * hinv, eh[j], 0.001f);
                    acc += hj;
                    ch[j + 1] = fmaf(2.f, acc, -1.f);
                }
            }
            ch[10] = 1.f;
            float hd[10];
            #pragma unroll
            for (int j = 0; j < 10; j++) hd[j] = ch[j + 1] - ch[j];

            const float spc = 0.53974215f;          // log(exp(0.999)-1)
            const float dvE = 0.001f + softplus_fast(spc);
            float dv[11];
            dv[0] = dvE; dv[10] = dvE;
            #pragma unroll
            for (int j = 1; j < 10; j++) dv[j] = 0.001f + softplus_fast(pv[19 + j]);

            const float xc = fminf(fmaxf(xv, -1.f), 1.f);
            float icw = cw[0], ibw = wd[0], ich = ch[0], ihh = hd[0];
            float d0 = dv[0], d1 = dv[1];
            #pragma unroll
            for (int k = 1; k < 10; k++) {
                if (xc >= cw[k]) {
                    icw = cw[k]; ibw = wd[k]; ich = ch[k]; ihh = hd[k];
                    d0 = dv[k]; d1 = dv[k + 1];
                }
            }

            const float idl   = ihh / ibw;
            const float theta = (xc - icw) / ibw;
            const float th2   = theta * theta;
            const float tt    = theta * (1.f - theta);
            const float numer = ihh * (idl * th2 + d0 * tt);
            const float denom = idl + (d0 + d1 - 2.f * idl) * tt;
            const float zin   = ich + numer / denom;
            const float omt   = 1.f - theta;
            const float dnum  = idl * idl * (d1 * th2 + 2.f * idl * tt + d0 * omt * omt);
            const float ladv  = __logf(dnum) - 2.f * __logf(denom);

            const bool inside = (xv >= -1.f) && (xv <= 1.f);
            out[((b * C_ + c) * HW) + y * WW + x0 + m] = inside ? zin : xv;
            ladsum += inside ? ladv : 0.f;
        }
    }

    // ---- deterministic block reduction of ladsum ----
    #pragma unroll
    for (int off = 16; off; off >>= 1)
        ladsum += __shfl_down_sync(0xffffffffu, ladsum, off);
    if (lane == 0) s_wr[wid] = ladsum;
    __syncthreads();
    if (tid == 0) {
        float s = 0.f;
        #pragma unroll
        for (int i = 0; i < 8; i++) s += s_wr[i];
        g_partial[(b * HH + y) * 2 + blockIdx.x] = s;
    }
}

// =========================================================================
__global__ void __launch_bounds__(256) reduce_kernel(float* __restrict__ out)
{
    const int b = blockIdx.x;
    const int tid = threadIdx.x;
    __shared__ double sd[256];
    double s = (double)g_partial[b * 512 + tid]
             + (double)g_partial[b * 512 + tid + 256];
    sd[tid] = s;
    __syncthreads();
    for (int off = 128; off; off >>= 1) {
        if (tid < off) sd[tid] += sd[tid + off];
        __syncthreads();
    }
    if (tid == 0) out[B_ * C_ * HW + b] = (float)sd[0];
}

// =========================================================================
extern "C" void kernel_launch(void* const* d_in, const int* in_sizes, int n_in,
                              void* d_out, int out_size)
{
    const float* x     = (const float*)d_in[0];
    const float* clean = (const float*)d_in[1];
    const float* W1    = (const float*)d_in[2];
    const float* b1    = (const float*)d_in[3];
    const float* W2    = (const float*)d_in[4];
    const float* b2    = (const float*)d_in[5];
    float* out = (float*)d_out;

    cudaFuncSetAttribute(conv2_fused_kernel,
                         cudaFuncAttributeMaxDynamicSharedMemorySize, SMEM_TC);

    conv1_kernel<<<dim3(256, 16), 256>>>(clean, W1, b1);
    prep_w_kernel<<<144, 256>>>(W2);
    conv2_fused_kernel<<<dim3(2, 256, 16), 256, SMEM_TC>>>(b2, x, out);
    reduce_kernel<<<16, 256>>>(out);
}

// round 11
// speedup vs baseline: 13.7003x; 1.2925x over previous
#include <cuda_runtime.h>
#include <cuda_fp16.h>
#include <cstdint>

#define B_   16
#define C_   4
#define HH   256
#define WW   256
#define HID  64
#define PCH  116          // C_*(3*10-1)
#define HW   (HH*WW)      // 65536

// ---------------- device scratch (no allocations allowed) ----------------
// hid as packed fp16x2, ic-contiguous per pixel: g_hidF[px*32 + p] = ic 2p,2p+1
__device__ __align__(16) uint32_t g_hidF[B_ * HW * 32];    // 134 MB
__device__ float g_partial[B_ * HH * 2];
// W2 in mma.m16n8k16 B-fragment layout, fp16
__device__ __align__(16) uint32_t g_WfHi[9 * 4 * 16 * 64];
// W1 in mma.m16n8k8 B-fragment layout, fp16: [chunk6][nt8][lane32]
__device__ __align__(16) uint32_t g_Wf1[6 * 8 * 32];

// ======================= helpers =====================
__device__ __forceinline__ uint32_t smem_to_u32(const void* p) {
    uint32_t a;
    asm("{ .reg .u64 t; cvta.to.shared.u64 t, %1; cvt.u32.u64 %0, t; }"
        : "=r"(a) : "l"(p));
    return a;
}
#define SMEM_SWIZZLE_128B(o) ((o) ^ (((o) >> 3) & 0x70))

#define STS128(r0, r1, r2, r3, a) \
    asm volatile("st.shared.v4.b32 [%0], {%1, %2, %3, %4};" \
        :: "r"(a), "r"(r0), "r"(r1), "r"(r2), "r"(r3) : "memory")

__device__ __forceinline__ void ldsm_x4(uint32_t* r, uint32_t addr) {
    asm volatile("ldmatrix.sync.aligned.m8n8.x4.shared.b16 {%0,%1,%2,%3}, [%4];"
        : "=r"(r[0]), "=r"(r[1]), "=r"(r[2]), "=r"(r[3]) : "r"(addr));
}
__device__ __forceinline__ void mma_f16(float* d, const uint32_t* a,
                                        const uint32_t* b) {
    asm volatile(
        "mma.sync.aligned.m16n8k16.row.col.f32.f16.f16.f32 "
        "{%0,%1,%2,%3}, {%4,%5,%6,%7}, {%8,%9}, {%0,%1,%2,%3};"
        : "+f"(d[0]), "+f"(d[1]), "+f"(d[2]), "+f"(d[3])
        : "r"(a[0]), "r"(a[1]), "r"(a[2]), "r"(a[3]),
          "r"(b[0]), "r"(b[1]));
}
__device__ __forceinline__ void mma_f16_k8(float* d, const uint32_t* a,
                                           uint32_t b) {
    asm volatile(
        "mma.sync.aligned.m16n8k8.row.col.f32.f16.f16.f32 "
        "{%0,%1,%2,%3}, {%4,%5}, {%6}, {%0,%1,%2,%3};"
        : "+f"(d[0]), "+f"(d[1]), "+f"(d[2]), "+f"(d[3])
        : "r"(a[0]), "r"(a[1]), "r"(b));
}

// =========================================================================
// prep_w1: pack W1 into m16n8k8 B-fragment layout, fp16.
// chunk = ky*2 + cb; k = p*4+ic; kx = cb? 2+p : p (kx==3 -> 0 pad).
// =========================================================================
__global__ void __launch_bounds__(256) prep_w1_kernel(const float* __restrict__ W1)
{
    const int i = blockIdx.x * 256 + threadIdx.x;
    if (i >= 6 * 8 * 32) return;
    const int lane  = i & 31;
    const int nt    = (i >> 5) & 7;
    const int chunk = i >> 8;
    const int ky = chunk >> 1, cb = chunk & 1;
    const int n  = nt * 8 + (lane >> 2);
    const int k0 = (lane & 3) * 2;

    float w[2];
    #pragma unroll
    for (int e = 0; e < 2; ++e) {
        const int ke = k0 + e;
        const int p = ke >> 2, ic = ke & 3;
        const int kx = cb ? (2 + p) : p;
        w[e] = (kx < 3) ? W1[n * 36 + ic * 9 + ky * 3 + kx] : 0.f;
    }
    const __half2 h = __floats2half2_rn(w[0], w[1]);
    g_Wf1[i] = *(const uint32_t*)&h;
}

// =========================================================================
// conv1 via HMMA fp16: clean -> relu(conv3x3) -> g_hidF (packed fp16).
// CTA = 128 pixels of one row y, all 64 oc. Stage clean ic-contiguous fp16;
// K = 6 chunks of 8 (3 ky x {kx01, kx2+pad}); A frags read by plain LDS.
// =========================================================================
__global__ void __launch_bounds__(256) conv1_tc_kernel(
    const float* __restrict__ clean,
    const float* __restrict__ b1)
{
    __shared__ uint2 s_cl[3][132];     // [ky][slot] = 4 ic fp16 (slot = x-x0+1)
    __shared__ float s_b1[64];
    const int tid = threadIdx.x, wid = tid >> 5, lane = tid & 31;
    const int x0 = blockIdx.x * 128;
    const int y  = blockIdx.y;
    const int b  = blockIdx.z;
    const int mg = wid & 3;            // m-group (32 rows)
    const int ng = wid >> 2;           // n-group (32 cols)

    if (tid < 64) s_b1[tid] = b1[tid];
    for (int i = tid; i < 3 * 131; i += 256) {
        const int ky = i / 131, s = i - ky * 131;
        const int yy = y + ky - 1, xx = x0 + s - 1;
        uint2 v = make_uint2(0, 0);
        if ((unsigned)yy < 256u && (unsigned)xx < 256u) {
            const int base = (b * 4) * HW + yy * WW + xx;
            const float c0 = clean[base];
            const float c1 = clean[base + HW];
            const float c2 = clean[base + 2 * HW];
            const float c3 = clean[base + 3 * HW];
            const __half2 h01 = __floats2half2_rn(c0, c1);
            const __half2 h23 = __floats2half2_rn(c2, c3);
            v.x = *(const uint32_t*)&h01;
            v.y = *(const uint32_t*)&h23;
        }
        s_cl[ky][s] = v;
    }
    __syncthreads();

    float d[2][4][4];
    #pragma unroll
    for (int mt = 0; mt < 2; ++mt)
        #pragma unroll
        for (int nt = 0; nt < 4; ++nt)
            #pragma unroll
            for (int r = 0; r < 4; ++r) d[mt][nt][r] = 0.f;

    const uint32_t sbcl = smem_to_u32(&s_cl[0][0]);
    const int q = lane & 3;
    #pragma unroll
    for (int chunk = 0; chunk < 6; ++chunk) {
        const int ky = chunk >> 1, cb = chunk & 1;
        const int so = (cb ? 2 : 0) + (q >> 1);
        uint32_t a[2][2];
        #pragma unroll
        for (int mt = 0; mt < 2; ++mt) {
            const int row = mg * 32 + mt * 16 + (lane >> 2);
            const uint32_t ad = sbcl + (uint32_t)((ky * 132 + row + so) * 8 + (q & 1) * 4);
            asm volatile("ld.shared.b32 %0, [%1];" : "=r"(a[mt][0]) : "r"(ad));
            asm volatile("ld.shared.b32 %0, [%1];" : "=r"(a[mt][1]) : "r"(ad + 64));
        }
        #pragma unroll
        for (int nt = 0; nt < 4; ++nt) {
            const uint32_t bw = g_Wf1[(chunk * 8 + ng * 4 + nt) * 32 + lane];
            #pragma unroll
            for (int mt = 0; mt < 2; ++mt)
                mma_f16_k8(d[mt][nt], a[mt], bw);
        }
    }

    // epilogue: bias + relu + fp16 pack -> g_hidF
    #pragma unroll
    for (int mt = 0; mt < 2; ++mt) {
        const int r0 = mg * 32 + mt * 16 + (lane >> 2);
        const size_t px0 = (size_t)(b * HH + y) * WW + x0 + r0;
        #pragma unroll
        for (int nt = 0; nt < 4; ++nt) {
            const int col = ng * 32 + nt * 8 + (lane & 3) * 2;
            const float bb0 = s_b1[col], bb1 = s_b1[col + 1];
            const __half2 h0 = __floats2half2_rn(fmaxf(d[mt][nt][0] + bb0, 0.f),
                                                 fmaxf(d[mt][nt][1] + bb1, 0.f));
            const __half2 h1 = __floats2half2_rn(fmaxf(d[mt][nt][2] + bb0, 0.f),
                                                 fmaxf(d[mt][nt][3] + bb1, 0.f));
            const int word = col >> 1;
            g_hidF[px0 * 32 + word]       = *(const uint32_t*)&h0;
            g_hidF[(px0 + 8) * 32 + word] = *(const uint32_t*)&h1;
        }
    }
}

// =========================================================================
// prep_w: pack W2 into mma B-fragment layout, fp16.
// =========================================================================
__global__ void __launch_bounds__(256) prep_w_kernel(const float* __restrict__ W2)
{
    const int i = blockIdx.x * 256 + threadIdx.x;
    if (i >= 9 * 4 * 16 * 64) return;
    const int r    = i & 1;
    const int lane = (i >> 1) & 31;
    const int nt   = (i >> 6) & 15;
    const int ks   = (i >> 10) & 3;
    const int j    = i >> 12;
    const int n    = nt * 8 + (lane >> 2);
    const int ic0  = ks * 16 + r * 8 + (lane & 3) * 2;

    float w0 = 0.f, w1 = 0.f;
    if (n < PCH) {
        w0 = W2[n * 576 + ic0 * 9 + j];
        w1 = W2[n * 576 + (ic0 + 1) * 9 + j];
    }
    const __half h0 = __float2half_rn(w0), h1 = __float2half_rn(w1);
    const uint16_t uh0 = *(const uint16_t*)&h0, uh1 = *(const uint16_t*)&h1;
    g_WfHi[i] = (uint32_t)uh0 | ((uint32_t)uh1 << 16);
}

// =========================================================================
// fused conv2 (HMMA fp16 single-pass) + bias + spline + lad reduction.
// 256 threads, 8 warps: warp tile 64(m) x 32(n). Single A buffer +
// register prefetch across the 3 ky chunks. 2 CTAs/SM overlap.
// =========================================================================
#define SMEM_TC  61440     // max(A buf 16640, s_out 116*132*4 = 61248)

__device__ __forceinline__ float softplus_fast(float t) {
    return fmaxf(t, 0.f) + __logf(1.f + __expf(-fabsf(t)));
}

__device__ __forceinline__ uint4 ld_gran(int b, int yy, int x0, int g) {
    const int mm = g >> 3, q = g & 7;
    const int xx = x0 + mm - 1;
    uint4 v = make_uint4(0, 0, 0, 0);
    if ((unsigned)yy < 256u && (unsigned)xx < 256u)
        v = *(const uint4*)&g_hidF[((size_t)(b * HH + yy) * WW + xx) * 32 + q * 4];
    return v;
}

__global__ void __launch_bounds__(256, 2) conv2_fused_kernel(
    const float* __restrict__ b2,
    const float* __restrict__ xin,
    float* __restrict__ out)
{
    extern __shared__ char smem[];
    __shared__ float s_b2[128];
    __shared__ float s_wr[8];
    const uint32_t sb = smem_to_u32(smem);
    const int tid = threadIdx.x, wid = tid >> 5, lane = tid & 31;
    const int x0 = blockIdx.x * 128;
    const int y  = blockIdx.y;
    const int b  = blockIdx.z;
    const int mg = wid & 1;          // m-group (64 rows)
    const int ng = wid >> 1;         // n-group (32 cols)

    if (tid < 128) s_b2[tid] = (tid < PCH) ? b2[tid] : 0.f;

    float d[4][4][4];
    #pragma unroll
    for (int mt = 0; mt < 4; ++mt)
        #pragma unroll
        for (int nt = 0; nt < 4; ++nt)
            #pragma unroll
            for (int r = 0; r < 4; ++r) d[mt][nt][r] = 0.f;

    // prefetch ky=0 (yy = y-1): 1040 granules = 4*256 + 16
    uint4 pf[4];
    #pragma unroll
    for (int q = 0; q < 4; ++q) pf[q] = ld_gran(b, y - 1, x0, tid + q * 256);
    uint4 pfT = (tid < 16) ? ld_gran(b, y - 1, x0, 1024 + tid)
                           : make_uint4(0, 0, 0, 0);

    for (int ky = 0; ky < 3; ++ky) {
        // ---- store prefetched granules (SW128) ----
        #pragma unroll
        for (int q = 0; q < 4; ++q) {
            const int g = tid + q * 256;
            STS128(pf[q].x, pf[q].y, pf[q].z, pf[q].w,
                   sb + SMEM_SWIZZLE_128B((uint32_t)((g >> 3) * 128 + (g & 7) * 16)));
        }
        if (tid < 16) {
            const int g = 1024 + tid;
            STS128(pfT.x, pfT.y, pfT.z, pfT.w,
                   sb + SMEM_SWIZZLE_128B((uint32_t)((g >> 3) * 128 + (g & 7) * 16)));
        }
        __syncthreads();

        // ---- prefetch next ky while MMAs run ----
        if (ky < 2) {
            #pragma unroll
            for (int q = 0; q < 4; ++q) pf[q] = ld_gran(b, y + ky, x0, tid + q * 256);
            if (tid < 16) pfT = ld_gran(b, y + ky, x0, 1024 + tid);
        }

        // ---- consume: 3 kx chunks x 4 K-steps ----
        for (int kx = 0; kx < 3; ++kx) {
            const int j = ky * 3 + kx;
            #pragma unroll
            for (int ks = 0; ks < 4; ++ks) {
                uint32_t ah[4][4];
                const uint32_t cbyte = ks * 32 + (lane >> 4) * 16;
                #pragma unroll
                for (int mt = 0; mt < 4; ++mt) {
                    const uint32_t row =
                        (uint32_t)(mg * 64 + mt * 16 + (lane & 15) + kx);
                    ldsm_x4(ah[mt], sb + SMEM_SWIZZLE_128B(row * 128 + cbyte));
                }
                uint32_t bh[4][2];
                #pragma unroll
                for (int nt4 = 0; nt4 < 4; ++nt4) {
                    const int nt = ng * 4 + nt4;
                    const int idx = ((j * 4 + ks) * 16 + nt) * 32 + lane;
                    const uint2 vh = ((const uint2*)g_WfHi)[idx];
                    bh[nt4][0] = vh.x; bh[nt4][1] = vh.y;
                }
                #pragma unroll
                for (int mt = 0; mt < 4; ++mt)
                    #pragma unroll
                    for (int nt4 = 0; nt4 < 4; ++nt4)
                        mma_f16(d[mt][nt4], ah[mt], bh[nt4]);
            }
        }
        __syncthreads();
    }

    // ---- stage result: s_out[n=0..115][m padded 132] ----
    float* s_out = (float*)smem;
    #pragma unroll
    for (int mt = 0; mt < 4; ++mt)
        #pragma unroll
        for (int nt4 = 0; nt4 < 4; ++nt4)
            #pragma unroll
            for (int r = 0; r < 4; ++r) {
                const int m = mg * 64 + mt * 16 + (lane >> 2) + ((r >> 1) * 8);
                const int n = ng * 32 + nt4 * 8 + (lane & 3) * 2 + (r & 1);
                if (n < PCH) s_out[n * 132 + m] = d[mt][nt4][r];
            }
    __syncthreads();

    // ---- fused spline: thread handles pixels m=tid&127 for c0, c0+2 ----
    float ladsum = 0.f;
    {
        const int m  = tid & 127;
        const int c0 = tid >> 7;
        #pragma unroll
        for (int e = 0; e < 2; ++e) {
            const int c = c0 + 2 * e;
            float pv[29];
            #pragma unroll
            for (int j = 0; j < 29; j++)
                pv[j] = s_out[(c * 29 + j) * 132 + m] + s_b2[c * 29 + j];

            const float xv = xin[((b * C_ + c) * HW) + y * WW + x0 + m];

            float uw[10];
            #pragma unroll
            for (int j = 0; j < 10; j++) uw[j] = pv[j] * 0.125f;
            float mw = uw[0];
            #pragma unroll
            for (int j = 1; j < 10; j++) mw = fmaxf(mw, uw[j]);
            float ew[10]; float ssum = 0.f;
            #pragma unroll
            for (int j = 0; j < 10; j++) { ew[j] = __expf(uw[j] - mw); ssum += ew[j]; }
            float inv = 1.0f / ssum;
            float cw[11]; cw[0] = -1.f;
            {
                float acc = 0.f;
                #pragma unroll
                for (int j = 0; j < 10; j++) {
                    float wj = fmaf(0.99f * inv, ew[j], 0.001f);
                    acc += wj;
                    cw[j + 1] = fmaf(2.f, acc, -1.f);
                }
            }
            cw[10] = 1.f;
            float wd[10];
            #pragma unroll
            for (int j = 0; j < 10; j++) wd[j] = cw[j + 1] - cw[j];

            float uh[10];
            #pragma unroll
            for (int j = 0; j < 10; j++) uh[j] = pv[10 + j] * 0.125f;
            float mh = uh[0];
            #pragma unroll
            for (int j = 1; j < 10; j++) mh = fmaxf(mh, uh[j]);
            float eh[10]; float hsum = 0.f;
            #pragma unroll
            for (int j = 0; j < 10; j++) { eh[j] = __expf(uh[j] - mh); hsum += eh[j]; }
            float hinv = 1.0f / hsum;
            float ch[11]; ch[0] = -1.f;
            {
                float acc = 0.f;
                #pragma unroll
                for (int j = 0; j < 10; j++) {
                    float hj = fmaf(0.99f * hinv, eh[j], 0.001f);
                    acc += hj;
                    ch[j + 1] = fmaf(2.f, acc, -1.f);
                }
            }
            ch[10] = 1.f;
            float hd[10];
            #pragma unroll
            for (int j = 0; j < 10; j++) hd[j] = ch[j + 1] - ch[j];

            const float spc = 0.53974215f;          // log(exp(0.999)-1)
            const float dvE = 0.001f + softplus_fast(spc);
            float dv[11];
            dv[0] = dvE; dv[10] = dvE;
            #pragma unroll
            for (int j = 1; j < 10; j++) dv[j] = 0.001f + softplus_fast(pv[19 + j]);

            const float xc = fminf(fmaxf(xv, -1.f), 1.f);
            float icw = cw[0], ibw = wd[0], ich = ch[0], ihh = hd[0];
            float d0 = dv[0], d1 = dv[1];
            #pragma unroll
            for (int k = 1; k < 10; k++) {
                if (xc >= cw[k]) {
                    icw = cw[k]; ibw = wd[k]; ich = ch[k]; ihh = hd[k];
                    d0 = dv[k]; d1 = dv[k + 1];
                }
            }

            const float idl   = ihh / ibw;
            const float theta = (xc - icw) / ibw;
            const float th2   = theta * theta;
            const float tt    = theta * (1.f - theta);
            const float numer = ihh * (idl * th2 + d0 * tt);
            const float denom = idl + (d0 + d1 - 2.f * idl) * tt;
            const float zin   = ich + numer / denom;
            const float omt   = 1.f - theta;
            const float dnum  = idl * idl * (d1 * th2 + 2.f * idl * tt + d0 * omt * omt);
            const float ladv  = __logf(dnum) - 2.f * __logf(denom);

            const bool inside = (xv >= -1.f) && (xv <= 1.f);
            out[((b * C_ + c) * HW) + y * WW + x0 + m] = inside ? zin : xv;
            ladsum += inside ? ladv : 0.f;
        }
    }

    // ---- deterministic block reduction of ladsum ----
    #pragma unroll
    for (int off = 16; off; off >>= 1)
        ladsum += __shfl_down_sync(0xffffffffu, ladsum, off);
    if (lane == 0) s_wr[wid] = ladsum;
    __syncthreads();
    if (tid == 0) {
        float s = 0.f;
        #pragma unroll
        for (int i = 0; i < 8; i++) s += s_wr[i];
        g_partial[(b * HH + y) * 2 + blockIdx.x] = s;
    }
}

// =========================================================================
__global__ void __launch_bounds__(256) reduce_kernel(float* __restrict__ out)
{
    const int b = blockIdx.x;
    const int tid = threadIdx.x;
    __shared__ double sd[256];
    double s = (double)g_partial[b * 512 + tid]
             + (double)g_partial[b * 512 + tid + 256];
    sd[tid] = s;
    __syncthreads();
    for (int off = 128; off; off >>= 1) {
        if (tid < off) sd[tid] += sd[tid + off];
        __syncthreads();
    }
    if (tid == 0) out[B_ * C_ * HW + b] = (float)sd[0];
}

// =========================================================================
extern "C" void kernel_launch(void* const* d_in, const int* in_sizes, int n_in,
                              void* d_out, int out_size)
{
    const float* x     = (const float*)d_in[0];
    const float* clean = (const float*)d_in[1];
    const float* W1    = (const float*)d_in[2];
    const float* b1    = (const float*)d_in[3];
    const float* W2    = (const float*)d_in[4];
    const float* b2    = (const float*)d_in[5];
    float* out = (float*)d_out;

    cudaFuncSetAttribute(conv2_fused_kernel,
                         cudaFuncAttributeMaxDynamicSharedMemorySize, SMEM_TC);

    prep_w1_kernel<<<6, 256>>>(W1);
    prep_w_kernel<<<144, 256>>>(W2);
    conv1_tc_kernel<<<dim3(2, 256, 16), 256>>>(clean, b1);
    conv2_fused_kernel<<<dim3(2, 256, 16), 256, SMEM_TC>>>(b2, x, out);
    reduce_kernel<<<16, 256>>>(out);
}

// round 12
// speedup vs baseline: 13.7761x; 1.0055x over previous
#include <cuda_runtime.h>
#include <cuda_fp16.h>
#include <cstdint>

#define B_   16
#define C_   4
#define HH   256
#define WW   256
#define HID  64
#define PCH  116          // C_*(3*10-1)
#define HW   (HH*WW)      // 65536

// ---------------- device scratch (no allocations allowed) ----------------
// hid as packed fp16x2, ic-contiguous per pixel: g_hidF[px*32 + p] = ic 2p,2p+1
__device__ __align__(16) uint32_t g_hidF[B_ * HW * 32];    // 134 MB
__device__ float g_partial[B_ * 256];
// W2 in mma.m16n8k16 B-fragment layout, fp16
__device__ __align__(16) uint32_t g_WfHi[9 * 4 * 16 * 64];
// W1 in mma.m16n8k8 B-fragment layout, fp16
__device__ __align__(16) uint32_t g_Wf1[6 * 8 * 32];

// ======================= helpers =====================
__device__ __forceinline__ uint32_t smem_to_u32(const void* p) {
    uint32_t a;
    asm("{ .reg .u64 t; cvta.to.shared.u64 t, %1; cvt.u32.u64 %0, t; }"
        : "=r"(a) : "l"(p));
    return a;
}
#define SMEM_SWIZZLE_128B(o) ((o) ^ (((o) >> 3) & 0x70))

__device__ __forceinline__ void cp_async16(uint32_t saddr, const void* gptr,
                                           int src_bytes) {
    asm volatile("cp.async.cg.shared.global [%0], [%1], 16, %2;"
        :: "r"(saddr), "l"(gptr), "r"(src_bytes));
}
#define CP_COMMIT() asm volatile("cp.async.commit_group;" ::: "memory")
#define CP_WAIT0()  asm volatile("cp.async.wait_group 0;" ::: "memory")

__device__ __forceinline__ void ldsm_x4(uint32_t* r, uint32_t addr) {
    asm volatile("ldmatrix.sync.aligned.m8n8.x4.shared.b16 {%0,%1,%2,%3}, [%4];"
        : "=r"(r[0]), "=r"(r[1]), "=r"(r[2]), "=r"(r[3]) : "r"(addr));
}
__device__ __forceinline__ void mma_f16(float* d, const uint32_t* a,
                                        const uint32_t* b) {
    asm volatile(
        "mma.sync.aligned.m16n8k16.row.col.f32.f16.f16.f32 "
        "{%0,%1,%2,%3}, {%4,%5,%6,%7}, {%8,%9}, {%0,%1,%2,%3};"
        : "+f"(d[0]), "+f"(d[1]), "+f"(d[2]), "+f"(d[3])
        : "r"(a[0]), "r"(a[1]), "r"(a[2]), "r"(a[3]),
          "r"(b[0]), "r"(b[1]));
}
__device__ __forceinline__ void mma_f16_k8(float* d, const uint32_t* a,
                                           uint32_t b) {
    asm volatile(
        "mma.sync.aligned.m16n8k8.row.col.f32.f16.f16.f32 "
        "{%0,%1,%2,%3}, {%4,%5}, {%6}, {%0,%1,%2,%3};"
        : "+f"(d[0]), "+f"(d[1]), "+f"(d[2]), "+f"(d[3])
        : "r"(a[0]), "r"(a[1]), "r"(b));
}

// =========================================================================
// prep_w1: pack W1 into m16n8k8 B-fragment layout, fp16.
// =========================================================================
__global__ void __launch_bounds__(256) prep_w1_kernel(const float* __restrict__ W1)
{
    const int i = blockIdx.x * 256 + threadIdx.x;
    if (i >= 6 * 8 * 32) return;
    const int lane  = i & 31;
    const int nt    = (i >> 5) & 7;
    const int chunk = i >> 8;
    const int ky = chunk >> 1, cb = chunk & 1;
    const int n  = nt * 8 + (lane >> 2);
    const int k0 = (lane & 3) * 2;

    float w[2];
    #pragma unroll
    for (int e = 0; e < 2; ++e) {
        const int ke = k0 + e;
        const int p = ke >> 2, ic = ke & 3;
        const int kx = cb ? (2 + p) : p;
        w[e] = (kx < 3) ? W1[n * 36 + ic * 9 + ky * 3 + kx] : 0.f;
    }
    const __half2 h = __floats2half2_rn(w[0], w[1]);
    g_Wf1[i] = *(const uint32_t*)&h;
}

// =========================================================================
// conv1 via HMMA fp16: clean -> relu(conv3x3) -> g_hidF (packed fp16).
// =========================================================================
__global__ void __launch_bounds__(256) conv1_tc_kernel(
    const float* __restrict__ clean,
    const float* __restrict__ b1)
{
    __shared__ uint2 s_cl[3][132];
    __shared__ float s_b1[64];
    const int tid = threadIdx.x, wid = tid >> 5, lane = tid & 31;
    const int x0 = blockIdx.x * 128;
    const int y  = blockIdx.y;
    const int b  = blockIdx.z;
    const int mg = wid & 3;
    const int ng = wid >> 2;

    if (tid < 64) s_b1[tid] = b1[tid];
    for (int i = tid; i < 3 * 131; i += 256) {
        const int ky = i / 131, s = i - ky * 131;
        const int yy = y + ky - 1, xx = x0 + s - 1;
        uint2 v = make_uint2(0, 0);
        if ((unsigned)yy < 256u && (unsigned)xx < 256u) {
            const int base = (b * 4) * HW + yy * WW + xx;
            const float c0 = clean[base];
            const float c1 = clean[base + HW];
            const float c2 = clean[base + 2 * HW];
            const float c3 = clean[base + 3 * HW];
            const __half2 h01 = __floats2half2_rn(c0, c1);
            const __half2 h23 = __floats2half2_rn(c2, c3);
            v.x = *(const uint32_t*)&h01;
            v.y = *(const uint32_t*)&h23;
        }
        s_cl[ky][s] = v;
    }
    __syncthreads();

    float d[2][4][4];
    #pragma unroll
    for (int mt = 0; mt < 2; ++mt)
        #pragma unroll
        for (int nt = 0; nt < 4; ++nt)
            #pragma unroll
            for (int r = 0; r < 4; ++r) d[mt][nt][r] = 0.f;

    const uint32_t sbcl = smem_to_u32(&s_cl[0][0]);
    const int q = lane & 3;
    #pragma unroll
    for (int chunk = 0; chunk < 6; ++chunk) {
        const int ky = chunk >> 1, cb = chunk & 1;
        const int so = (cb ? 2 : 0) + (q >> 1);
        uint32_t a[2][2];
        #pragma unroll
        for (int mt = 0; mt < 2; ++mt) {
            const int row = mg * 32 + mt * 16 + (lane >> 2);
            const uint32_t ad = sbcl + (uint32_t)((ky * 132 + row + so) * 8 + (q & 1) * 4);
            asm volatile("ld.shared.b32 %0, [%1];" : "=r"(a[mt][0]) : "r"(ad));
            asm volatile("ld.shared.b32 %0, [%1];" : "=r"(a[mt][1]) : "r"(ad + 64));
        }
        #pragma unroll
        for (int nt = 0; nt < 4; ++nt) {
            const uint32_t bw = g_Wf1[(chunk * 8 + ng * 4 + nt) * 32 + lane];
            #pragma unroll
            for (int mt = 0; mt < 2; ++mt)
                mma_f16_k8(d[mt][nt], a[mt], bw);
        }
    }

    #pragma unroll
    for (int mt = 0; mt < 2; ++mt) {
        const int r0 = mg * 32 + mt * 16 + (lane >> 2);
        const size_t px0 = (size_t)(b * HH + y) * WW + x0 + r0;
        #pragma unroll
        for (int nt = 0; nt < 4; ++nt) {
            const int col = ng * 32 + nt * 8 + (lane & 3) * 2;
            const float bb0 = s_b1[col], bb1 = s_b1[col + 1];
            const __half2 h0 = __floats2half2_rn(fmaxf(d[mt][nt][0] + bb0, 0.f),
                                                 fmaxf(d[mt][nt][1] + bb1, 0.f));
            const __half2 h1 = __floats2half2_rn(fmaxf(d[mt][nt][2] + bb0, 0.f),
                                                 fmaxf(d[mt][nt][3] + bb1, 0.f));
            const int word = col >> 1;
            g_hidF[px0 * 32 + word]       = *(const uint32_t*)&h0;
            g_hidF[(px0 + 8) * 32 + word] = *(const uint32_t*)&h1;
        }
    }
}

// =========================================================================
// prep_w: pack W2 into mma B-fragment layout, fp16.
// =========================================================================
__global__ void __launch_bounds__(256) prep_w_kernel(const float* __restrict__ W2)
{
    const int i = blockIdx.x * 256 + threadIdx.x;
    if (i >= 9 * 4 * 16 * 64) return;
    const int r    = i & 1;
    const int lane = (i >> 1) & 31;
    const int nt   = (i >> 6) & 15;
    const int ks   = (i >> 10) & 3;
    const int j    = i >> 12;
    const int n    = nt * 8 + (lane >> 2);
    const int ic0  = ks * 16 + r * 8 + (lane & 3) * 2;

    float w0 = 0.f, w1 = 0.f;
    if (n < PCH) {
        w0 = W2[n * 576 + ic0 * 9 + j];
        w1 = W2[n * 576 + (ic0 + 1) * 9 + j];
    }
    const __half h0 = __float2half_rn(w0), h1 = __float2half_rn(w1);
    const uint16_t uh0 = *(const uint16_t*)&h0, uh1 = *(const uint16_t*)&h1;
    g_WfHi[i] = (uint32_t)uh0 | ((uint32_t)uh1 << 16);
}

// =========================================================================
// fused conv2 (HMMA fp16) + bias + spline + lad reduction.
// CTA = 2-row tile (M=256 pixels) x 128 (padded) oc. 512 threads / 16 warps,
// warp tile 64(m) x 32(n). 4 input-row fp16 planes loaded once via cp.async;
// all 36 K-chunks run barrier-free (plane = ky + row-half).
// =========================================================================
#define PLANE_B  16640                 // 130 slots * 128 B
#define SMEM_TC  122496                // s_out 116*264*4 (A planes 66560 overlap)

__device__ __forceinline__ float softplus_fast(float t) {
    return fmaxf(t, 0.f) + __logf(1.f + __expf(-fabsf(t)));
}

__global__ void __launch_bounds__(512, 1) conv2_fused_kernel(
    const float* __restrict__ b2,
    const float* __restrict__ xin,
    float* __restrict__ out)
{
    extern __shared__ char smem[];
    __shared__ float s_b2[128];
    __shared__ float s_wr[16];
    const uint32_t sb = smem_to_u32(smem);
    const int tid = threadIdx.x, wid = tid >> 5, lane = tid & 31;
    const int x0 = blockIdx.x * 128;
    const int y0 = blockIdx.y * 2;
    const int b  = blockIdx.z;
    const int mg = wid & 3;            // m-group (64 rows of 256)
    const int ng = wid >> 2;           // n-group (32 cols of 128)

    if (tid < 128) s_b2[tid] = (tid < PCH) ? b2[tid] : 0.f;

    // ---- build 4 input-row planes (y0-1 .. y0+2) via cp.async ----
    for (int g = tid; g < 4 * 130 * 8; g += 512) {
        const int p = g / 1040, rem = g - p * 1040;
        const int s = rem >> 3, q = rem & 7;
        const int yy = y0 + p - 1, xx = x0 + s - 1;
        const bool ok = ((unsigned)yy < 256u) && ((unsigned)xx < 256u);
        const size_t px = ok ? ((size_t)(b * HH + yy) * WW + xx) : 0;
        const uint32_t sa = sb + p * PLANE_B
                          + SMEM_SWIZZLE_128B((uint32_t)(s * 128 + q * 16));
        cp_async16(sa, &g_hidF[px * 32 + q * 4], ok ? 16 : 0);
    }
    CP_COMMIT();
    CP_WAIT0();
    __syncthreads();

    float d[4][4][4];
    #pragma unroll
    for (int mt = 0; mt < 4; ++mt)
        #pragma unroll
        for (int nt = 0; nt < 4; ++nt)
            #pragma unroll
            for (int r = 0; r < 4; ++r) d[mt][nt][r] = 0.f;

    // ---- barrier-free MMA phase: 3 ky x 3 kx x 4 ks ----
    const uint32_t planeBase = sb + (mg >> 1) * PLANE_B;   // half-row offset
    #pragma unroll
    for (int ky = 0; ky < 3; ++ky) {
        const uint32_t pb = planeBase + ky * PLANE_B;
        #pragma unroll
        for (int kx = 0; kx < 3; ++kx) {
            const int j = ky * 3 + kx;
            #pragma unroll
            for (int ks = 0; ks < 4; ++ks) {
                uint32_t ah[4][4];
                const uint32_t cbyte = ks * 32 + (lane >> 4) * 16;
                #pragma unroll
                for (int mt = 0; mt < 4; ++mt) {
                    const uint32_t row =
                        (uint32_t)((mg & 1) * 64 + mt * 16 + (lane & 15) + kx);
                    ldsm_x4(ah[mt], pb + SMEM_SWIZZLE_128B(row * 128 + cbyte));
                }
                uint32_t bh[4][2];
                #pragma unroll
                for (int nt4 = 0; nt4 < 4; ++nt4) {
                    const int nt = ng * 4 + nt4;
                    const int idx = ((j * 4 + ks) * 16 + nt) * 32 + lane;
                    const uint2 vh = ((const uint2*)g_WfHi)[idx];
                    bh[nt4][0] = vh.x; bh[nt4][1] = vh.y;
                }
                #pragma unroll
                for (int mt = 0; mt < 4; ++mt)
                    #pragma unroll
                    for (int nt4 = 0; nt4 < 4; ++nt4)
                        mma_f16(d[mt][nt4], ah[mt], bh[nt4]);
            }
        }
    }
    __syncthreads();     // all A consumed; reuse smem for s_out

    // ---- stage result: s_out[n=0..115][m padded 264] ----
    float* s_out = (float*)smem;
    #pragma unroll
    for (int mt = 0; mt < 4; ++mt)
        #pragma unroll
        for (int nt4 = 0; nt4 < 4; ++nt4)
            #pragma unroll
            for (int r = 0; r < 4; ++r) {
                const int m = mg * 64 + mt * 16 + (lane >> 2) + ((r >> 1) * 8);
                const int n = ng * 32 + nt4 * 8 + (lane & 3) * 2 + (r & 1);
                if (n < PCH) s_out[n * 264 + m] = d[mt][nt4][r];
            }
    __syncthreads();

    // ---- fused spline: 1024 (c,pixel) units, 2 per thread ----
    float ladsum = 0.f;
    #pragma unroll
    for (int e = 0; e < 2; ++e) {
        const int u = tid + e * 512;
        const int m = u & 255;
        const int c = u >> 8;
        const int yr = y0 + (m >> 7);
        const int xc_ = x0 + (m & 127);
        float pv[29];
        #pragma unroll
        for (int j = 0; j < 29; j++)
            pv[j] = s_out[(c * 29 + j) * 264 + m] + s_b2[c * 29 + j];

        const float xv = xin[((b * C_ + c) * HW) + yr * WW + xc_];

        float uw[10];
        #pragma unroll
        for (int j = 0; j < 10; j++) uw[j] = pv[j] * 0.125f;
        float mw = uw[0];
        #pragma unroll
        for (int j = 1; j < 10; j++) mw = fmaxf(mw, uw[j]);
        float ew[10]; float ssum = 0.f;
        #pragma unroll
        for (int j = 0; j < 10; j++) { ew[j] = __expf(uw[j] - mw); ssum += ew[j]; }
        float inv = 1.0f / ssum;
        float cw[11]; cw[0] = -1.f;
        {
            float acc = 0.f;
            #pragma unroll
            for (int j = 0; j < 10; j++) {
                float wj = fmaf(0.99f * inv, ew[j], 0.001f);
                acc += wj;
                cw[j + 1] = fmaf(2.f, acc, -1.f);
            }
        }
        cw[10] = 1.f;
        float wd[10];
        #pragma unroll
        for (int j = 0; j < 10; j++) wd[j] = cw[j + 1] - cw[j];

        float uh[10];
        #pragma unroll
        for (int j = 0; j < 10; j++) uh[j] = pv[10 + j] * 0.125f;
        float mh = uh[0];
        #pragma unroll
        for (int j = 1; j < 10; j++) mh = fmaxf(mh, uh[j]);
        float eh[10]; float hsum = 0.f;
        #pragma unroll
        for (int j = 0; j < 10; j++) { eh[j] = __expf(uh[j] - mh); hsum += eh[j]; }
        float hinv = 1.0f / hsum;
        float ch[11]; ch[0] = -1.f;
        {
            float acc = 0.f;
            #pragma unroll
            for (int j = 0; j < 10; j++) {
                float hj = fmaf(0.99f * hinv, eh[j], 0.001f);
                acc += hj;
                ch[j + 1] = fmaf(2.f, acc, -1.f);
            }
        }
        ch[10] = 1.f;
        float hd[10];
        #pragma unroll
        for (int j = 0; j < 10; j++) hd[j] = ch[j + 1] - ch[j];

        const float spc = 0.53974215f;          // log(exp(0.999)-1)
        const float dvE = 0.001f + softplus_fast(spc);
        float dv[11];
        dv[0] = dvE; dv[10] = dvE;
        #pragma unroll
        for (int j = 1; j < 10; j++) dv[j] = 0.001f + softplus_fast(pv[19 + j]);

        const float xc = fminf(fmaxf(xv, -1.f), 1.f);
        float icw = cw[0], ibw = wd[0], ich = ch[0], ihh = hd[0];
        float d0 = dv[0], d1 = dv[1];
        #pragma unroll
        for (int k = 1; k < 10; k++) {
            if (xc >= cw[k]) {
                icw = cw[k]; ibw = wd[k]; ich = ch[k]; ihh = hd[k];
                d0 = dv[k]; d1 = dv[k + 1];
            }
        }

        const float idl   = ihh / ibw;
        const float theta = (xc - icw) / ibw;
        const float th2   = theta * theta;
        const float tt    = theta * (1.f - theta);
        const float numer = ihh * (idl * th2 + d0 * tt);
        const float denom = idl + (d0 + d1 - 2.f * idl) * tt;
        const float zin   = ich + numer / denom;
        const float omt   = 1.f - theta;
        const float dnum  = idl * idl * (d1 * th2 + 2.f * idl * tt + d0 * omt * omt);
        const float ladv  = __logf(dnum) - 2.f * __logf(denom);

        const bool inside = (xv >= -1.f) && (xv <= 1.f);
        out[((b * C_ + c) * HW) + yr * WW + xc_] = inside ? zin : xv;
        ladsum += inside ? ladv : 0.f;
    }

    // ---- deterministic block reduction of ladsum ----
    #pragma unroll
    for (int off = 16; off; off >>= 1)
        ladsum += __shfl_down_sync(0xffffffffu, ladsum, off);
    if (lane == 0) s_wr[wid] = ladsum;
    __syncthreads();
    if (tid == 0) {
        float s = 0.f;
        #pragma unroll
        for (int i = 0; i < 16; i++) s += s_wr[i];
        g_partial[(b * 128 + blockIdx.y) * 2 + blockIdx.x] = s;
    }
}

// =========================================================================
__global__ void __launch_bounds__(256) reduce_kernel(float* __restrict__ out)
{
    const int b = blockIdx.x;
    const int tid = threadIdx.x;
    __shared__ double sd[256];
    sd[tid] = (double)g_partial[b * 256 + tid];
    __syncthreads();
    for (int off = 128; off; off >>= 1) {
        if (tid < off) sd[tid] += sd[tid + off];
        __syncthreads();
    }
    if (tid == 0) out[B_ * C_ * HW + b] = (float)sd[0];
}

// =========================================================================
extern "C" void kernel_launch(void* const* d_in, const int* in_sizes, int n_in,
                              void* d_out, int out_size)
{
    const float* x     = (const float*)d_in[0];
    const float* clean = (const float*)d_in[1];
    const float* W1    = (const float*)d_in[2];
    const float* b1    = (const float*)d_in[3];
    const float* W2    = (const float*)d_in[4];
    const float* b2    = (const float*)d_in[5];
    float* out = (float*)d_out;

    cudaFuncSetAttribute(conv2_fused_kernel,
                         cudaFuncAttributeMaxDynamicSharedMemorySize, SMEM_TC);

    prep_w1_kernel<<<6, 256>>>(W1);
    prep_w_kernel<<<144, 256>>>(W2);
    conv1_tc_kernel<<<dim3(2, 256, 16), 256>>>(clean, b1);
    conv2_fused_kernel<<<dim3(2, 128, 16), 512, SMEM_TC>>>(b2, x, out);
    reduce_kernel<<<16, 256>>>(out);
}